// round 11
// baseline (speedup 1.0000x reference)
#include <cuda_runtime.h>
#include <cuda_fp16.h>
#include <stdint.h>
#include <math.h>

// ---------------------------------------------------------------------------
// Problem dims
// ---------------------------------------------------------------------------
#define B_SZ   16384
#define D_IN   1280
#define D_HID  512
#define D_OUT  229
#define K1     (7 * D_IN)    // 8960
#define K2     (7 * D_HID)   // 3584
#define N2PAD  256

// ---------------------------------------------------------------------------
// Scratch
// ---------------------------------------------------------------------------
static __device__ __half g_A1[(size_t)B_SZ * K1];
static __device__ __half g_W1[(size_t)D_HID * K1];
static __device__ float  g_h [(size_t)B_SZ * D_HID];
static __device__ __half g_A2[(size_t)B_SZ * K2];
static __device__ __half g_W2[(size_t)N2PAD * K2];

// ---------------------------------------------------------------------------
// Closed-form uniform cubic B-spline bases — static indexing (spill-free, R9)
// ---------------------------------------------------------------------------
__device__ __forceinline__ void kan_bases(float x, float bs[6]) {
    const float s  = (x + 3.0f) * 1.5f;
    const float cf = floorf(s);
    const int   c  = (int)cf;
    const float u  = s - cf;
    const float u2 = u * u;
    const float u3 = u2 * u;
    const float om = 1.0f - u;
    const float seg0 = om * om * om * (1.0f / 6.0f);
    const float seg1 = (3.0f * u3 - 6.0f * u2 + 4.0f) * (1.0f / 6.0f);
    const float seg2 = (-3.0f * u3 + 3.0f * u2 + 3.0f * u + 1.0f) * (1.0f / 6.0f);
    const float seg3 = u3 * (1.0f / 6.0f);
#pragma unroll
    for (int j = 0; j < 6; ++j) {
        float v = 0.0f;
        v = (c == j    ) ? seg3 : v;
        v = (c == j + 1) ? seg2 : v;
        v = (c == j + 2) ? seg1 : v;
        v = (c == j + 3) ? seg0 : v;
        bs[j] = v;
    }
}

__device__ __forceinline__ float silu_f(float v) { return v / (1.0f + expf(-v)); }

// ---------------------------------------------------------------------------
// Merged prep kernel (R9 champion structure): expand1 + fusew1 + fusew2
// ---------------------------------------------------------------------------
#define E1_BLOCKS (B_SZ * (D_IN / 2) / 256)      // 40960
#define F1_BLOCKS (D_HID * D_IN / 256)            // 2560
#define F2_BLOCKS (N2PAD * D_HID / 256)           // 512
#define PREP_BLOCKS (E1_BLOCKS + F1_BLOCKS + F2_BLOCKS)

__global__ __launch_bounds__(256) void prep_kernel(
    const float* __restrict__ x,
    const float* __restrict__ bw1, const float* __restrict__ sw1,
    const float* __restrict__ sc1,
    const float* __restrict__ bw2, const float* __restrict__ sw2,
    const float* __restrict__ sc2)
{
    const int blk = blockIdx.x;
    if (blk < E1_BLOCKS) {
        int idx = blk * 256 + threadIdx.x;
        int b  = idx / (D_IN / 2);
        int i2 = (idx - b * (D_IN / 2)) * 2;
        float2 v = *reinterpret_cast<const float2*>(x + (size_t)b * D_IN + i2);
        float bs0[6], bs1[6];
        kan_bases(v.x, bs0);
        kan_bases(v.y, bs1);
        size_t base = (size_t)b * K1 + i2;
        *reinterpret_cast<__half2*>(&g_A1[base]) =
            __floats2half2_rn(silu_f(v.x), silu_f(v.y));
#pragma unroll
        for (int j = 0; j < 6; ++j)
            *reinterpret_cast<__half2*>(&g_A1[base + (size_t)(j + 1) * D_IN]) =
                __floats2half2_rn(bs0[j], bs1[j]);
    } else if (blk < E1_BLOCKS + F1_BLOCKS) {
        int idx = (blk - E1_BLOCKS) * 256 + threadIdx.x;
        int o = idx / D_IN;
        int i = idx - o * D_IN;
        size_t base = (size_t)o * K1 + i;
        g_W1[base] = __float2half(bw1[idx]);
        float s = sc1[idx];
#pragma unroll
        for (int j = 0; j < 6; ++j)
            g_W1[base + (size_t)(j + 1) * D_IN] =
                __float2half(sw1[(size_t)idx * 6 + j] * s);
    } else {
        int idx = (blk - E1_BLOCKS - F1_BLOCKS) * 256 + threadIdx.x;
        int o = idx / D_HID;
        int c = idx - o * D_HID;
        size_t base = (size_t)o * K2 + c;
        if (o < D_OUT) {
            size_t widx = (size_t)o * D_HID + c;
            g_W2[base] = __float2half(bw2[widx]);
            float s = sc2[widx];
#pragma unroll
            for (int j = 0; j < 6; ++j)
                g_W2[base + (size_t)(j + 1) * D_HID] =
                    __float2half(sw2[widx * 6 + j] * s);
        } else {
            g_W2[base] = __float2half(0.0f);
#pragma unroll
            for (int j = 0; j < 6; ++j)
                g_W2[base + (size_t)(j + 1) * D_HID] = __float2half(0.0f);
        }
    }
}

// ---------------------------------------------------------------------------
// LayerNorm + expansion (R9 champion structure)
// ---------------------------------------------------------------------------
__global__ __launch_bounds__(256) void ln_expand2_kernel(
    const float* __restrict__ gamma, const float* __restrict__ beta)
{
    int row = blockIdx.x;
    int t = threadIdx.x;
    const float* hr = g_h + (size_t)row * D_HID;
    float2 v = *reinterpret_cast<const float2*>(hr + 2 * t);

    __shared__ float red[8];
    float s = v.x + v.y;
#pragma unroll
    for (int o = 16; o; o >>= 1) s += __shfl_down_sync(0xffffffffu, s, o);
    if ((t & 31) == 0) red[t >> 5] = s;
    __syncthreads();
    float tot = 0.0f;
#pragma unroll
    for (int i = 0; i < 8; ++i) tot += red[i];
    float mean = tot * (1.0f / (float)D_HID);
    __syncthreads();

    float d0 = v.x - mean, d1 = v.y - mean;
    float q = d0 * d0 + d1 * d1;
#pragma unroll
    for (int o = 16; o; o >>= 1) q += __shfl_down_sync(0xffffffffu, q, o);
    if ((t & 31) == 0) red[t >> 5] = q;
    __syncthreads();
    float qt = 0.0f;
#pragma unroll
    for (int i = 0; i < 8; ++i) qt += red[i];
    float inv = rsqrtf(qt * (1.0f / (float)D_HID) + 1e-5f);

    const int c = 2 * t;
    float y0 = d0 * inv * gamma[c]     + beta[c];
    float y1 = d1 * inv * gamma[c + 1] + beta[c + 1];
    float bs0[6], bs1[6];
    kan_bases(y0, bs0);
    kan_bases(y1, bs1);
    size_t base = (size_t)row * K2 + c;
    *reinterpret_cast<__half2*>(&g_A2[base]) =
        __floats2half2_rn(silu_f(y0), silu_f(y1));
#pragma unroll
    for (int j = 0; j < 6; ++j)
        *reinterpret_cast<__half2*>(&g_A2[base + (size_t)(j + 1) * D_HID]) =
            __floats2half2_rn(bs0[j], bs1[j]);
}

// ---------------------------------------------------------------------------
// HMMA GEMM with f16 accumulators + fp32 promotion every 2 k16 steps.
// Block 128x128x64, 1024 threads (32 warps = 4M x 8N), warp tile 32x16.
// 1 CTA/SM (32 warps). 5-stage cp.async ring. 144B smem rows.
// Theory: mma.sync f32-acc is half-rate on sm_103a legacy path; f16-acc
// with chunked fp32 promotion recovers 2x at ~1e-4 extra error.
// ---------------------------------------------------------------------------
#define BM 128
#define BN 128
#define BK 64
#define ROWB 144u
#define STG_B (uint32_t)((BM + BN) * ROWB)   // 36864 B
#define NSTG 5

template <int L>
__global__ __launch_bounds__(1024, 1) void gemm_hmma(float* __restrict__ Cparam) {
    constexpr int KK = (L == 1) ? K1 : K2;
    constexpr int NV = (L == 1) ? D_HID : D_OUT;
    constexpr int KT = KK / BK;

    const __half* __restrict__ A  = (L == 1) ? g_A1 : g_A2;
    const __half* __restrict__ Bw = (L == 1) ? g_W1 : g_W2;
    float* __restrict__ C         = (L == 1) ? g_h  : Cparam;

    extern __shared__ __half smh[];
    const uint32_t sbase = (uint32_t)__cvta_generic_to_shared(smh);

    const int tid  = threadIdx.x;
    const int warp = tid >> 5;
    const int lane = tid & 31;
    const int wm = (warp & 3) * 32;     // 4 M-positions
    const int wn = (warp >> 2) * 16;    // 8 N-positions
    const int mb = blockIdx.y;
    const int nb = blockIdx.x;

    const __half* Abase = A  + (size_t)(mb * BM) * KK;
    const __half* Bbase = Bw + (size_t)(nb * BN) * KK;

    auto issue = [&](int kt) {
        const uint32_t sb = sbase + (uint32_t)(kt % NSTG) * STG_B;
        {   // A: 128 rows x 8 chunks of 16B = 1024 chunks, 1 per thread
            const int r = tid >> 3, c = tid & 7;
            const void* src = Abase + (size_t)r * KK + kt * BK + c * 8;
            const uint32_t dst = sb + (uint32_t)r * ROWB + (uint32_t)c * 16u;
            asm volatile("cp.async.cg.shared.global [%0], [%1], 16;"
                         :: "r"(dst), "l"(src));
        }
        {   // B: 128 rows x 8 chunks, 1 per thread
            const int r = tid >> 3, c = tid & 7;
            const void* src = Bbase + (size_t)r * KK + kt * BK + c * 8;
            const uint32_t dst = sb + (uint32_t)BM * ROWB
                               + (uint32_t)r * ROWB + (uint32_t)c * 16u;
            asm volatile("cp.async.cg.shared.global [%0], [%1], 16;"
                         :: "r"(dst), "l"(src));
        }
        asm volatile("cp.async.commit_group;" ::: "memory");
    };

    float acc[2][2][4] = {};

    issue(0); issue(1); issue(2); issue(3);

    const int lrow = lane & 15;
    const int lcb  = (lane >> 4) * 8;
    const uint32_t zero = 0u;

#pragma unroll 1
    for (int kt = 0; kt < KT; ++kt) {
        const int rem = KT - 1 - kt;
        if      (rem >= 3) asm volatile("cp.async.wait_group 3;" ::: "memory");
        else if (rem == 2) asm volatile("cp.async.wait_group 2;" ::: "memory");
        else if (rem == 1) asm volatile("cp.async.wait_group 1;" ::: "memory");
        else               asm volatile("cp.async.wait_group 0;" ::: "memory");
        __syncthreads();
        if (kt + 4 < KT) issue(kt + 4);

        const uint32_t sb = sbase + (uint32_t)(kt % NSTG) * STG_B;
#pragma unroll
        for (int ks2 = 0; ks2 < 2; ++ks2) {
            uint32_t hacc[2][2][2];
#pragma unroll
            for (int s = 0; s < 2; ++s) {
                const int ks = ks2 * 2 + s;
                uint32_t a[2][4];
                uint32_t bq[4];
#pragma unroll
                for (int mt = 0; mt < 2; ++mt) {
                    const uint32_t addr = sb + (uint32_t)(wm + mt * 16 + lrow) * ROWB
                                        + (uint32_t)(ks * 16 + lcb) * 2u;
                    asm volatile("ldmatrix.sync.aligned.m8n8.x4.shared.b16 {%0,%1,%2,%3}, [%4];"
                                 : "=r"(a[mt][0]), "=r"(a[mt][1]), "=r"(a[mt][2]), "=r"(a[mt][3])
                                 : "r"(addr));
                }
                {
                    const uint32_t addr = sb + (uint32_t)BM * ROWB
                                        + (uint32_t)(wn + lrow) * ROWB
                                        + (uint32_t)(ks * 16 + lcb) * 2u;
                    asm volatile("ldmatrix.sync.aligned.m8n8.x4.shared.b16 {%0,%1,%2,%3}, [%4];"
                                 : "=r"(bq[0]), "=r"(bq[1]), "=r"(bq[2]), "=r"(bq[3])
                                 : "r"(addr));
                }
#pragma unroll
                for (int mt = 0; mt < 2; ++mt) {
#pragma unroll
                    for (int nt = 0; nt < 2; ++nt) {
                        if (s == 0) {
                            asm volatile(
                                "mma.sync.aligned.m16n8k16.row.col.f16.f16.f16.f16 "
                                "{%0,%1}, {%2,%3,%4,%5}, {%6,%7}, {%8,%8};"
                                : "=r"(hacc[mt][nt][0]), "=r"(hacc[mt][nt][1])
                                : "r"(a[mt][0]), "r"(a[mt][1]), "r"(a[mt][2]), "r"(a[mt][3]),
                                  "r"(bq[nt]), "r"(bq[nt + 2]), "r"(zero));
                        } else {
                            asm volatile(
                                "mma.sync.aligned.m16n8k16.row.col.f16.f16.f16.f16 "
                                "{%0,%1}, {%2,%3,%4,%5}, {%6,%7}, {%0,%1};"
                                : "+r"(hacc[mt][nt][0]), "+r"(hacc[mt][nt][1])
                                : "r"(a[mt][0]), "r"(a[mt][1]), "r"(a[mt][2]), "r"(a[mt][3]),
                                  "r"(bq[nt]), "r"(bq[nt + 2]));
                        }
                    }
                }
            }
            // promote chunk (K=32) into fp32 accumulators
#pragma unroll
            for (int mt = 0; mt < 2; ++mt) {
#pragma unroll
                for (int nt = 0; nt < 2; ++nt) {
                    float2 f0 = __half22float2(
                        *reinterpret_cast<__half2*>(&hacc[mt][nt][0]));
                    float2 f1 = __half22float2(
                        *reinterpret_cast<__half2*>(&hacc[mt][nt][1]));
                    acc[mt][nt][0] += f0.x;
                    acc[mt][nt][1] += f0.y;
                    acc[mt][nt][2] += f1.x;
                    acc[mt][nt][3] += f1.y;
                }
            }
        }
    }

    // ---- epilogue ----
    const int gr = lane >> 2;
    const int gc = (lane & 3) * 2;
#pragma unroll
    for (int mt = 0; mt < 2; ++mt) {
#pragma unroll
        for (int nt = 0; nt < 2; ++nt) {
            const int row = mb * BM + wm + mt * 16 + gr;
            const int col = nb * BN + wn + nt * 8 + gc;
            float* cp = C + (size_t)row * NV;
            if (NV % BN == 0) {
                cp[col]     = acc[mt][nt][0];
                cp[col + 1] = acc[mt][nt][1];
                cp += (size_t)8 * NV;
                cp[col]     = acc[mt][nt][2];
                cp[col + 1] = acc[mt][nt][3];
            } else {
                if (col < NV)     cp[col]     = acc[mt][nt][0];
                if (col + 1 < NV) cp[col + 1] = acc[mt][nt][1];
                cp += (size_t)8 * NV;
                if (col < NV)     cp[col]     = acc[mt][nt][2];
                if (col + 1 < NV) cp[col + 1] = acc[mt][nt][3];
            }
        }
    }
}

// ---------------------------------------------------------------------------
// Launch
// ---------------------------------------------------------------------------
#define GEMM_SMEM (NSTG * (int)STG_B)   // 184320 B

extern "C" void kernel_launch(void* const* d_in, const int* in_sizes, int n_in,
                              void* d_out, int out_size) {
    (void)in_sizes; (void)n_in; (void)out_size;
    const float* x   = (const float*)d_in[0];
    const float* bw1 = (const float*)d_in[1];
    const float* sw1 = (const float*)d_in[2];
    const float* sc1 = (const float*)d_in[3];
    const float* ga  = (const float*)d_in[4];
    const float* be  = (const float*)d_in[5];
    const float* bw2 = (const float*)d_in[6];
    const float* sw2 = (const float*)d_in[7];
    const float* sc2 = (const float*)d_in[8];
    float* out = (float*)d_out;

    cudaFuncSetAttribute(gemm_hmma<1>,
                         cudaFuncAttributeMaxDynamicSharedMemorySize, GEMM_SMEM);
    cudaFuncSetAttribute(gemm_hmma<2>,
                         cudaFuncAttributeMaxDynamicSharedMemorySize, GEMM_SMEM);

    // One merged prep launch: expand1 + fusew1 + fusew2
    prep_kernel<<<PREP_BLOCKS, 256>>>(x, bw1, sw1, sc1, bw2, sw2, sc2);

    // GEMM1: 512 CTAs (4 x 128), 1024 threads
    gemm_hmma<1><<<dim3(4, 128), 1024, GEMM_SMEM>>>(nullptr);

    ln_expand2_kernel<<<B_SZ, 256>>>(ga, be);

    // GEMM2: 256 CTAs (2 x 128), 1024 threads
    gemm_hmma<2><<<dim3(2, 128), 1024, GEMM_SMEM>>>(out);
}

// round 12
// speedup vs baseline: 1.0820x; 1.0820x over previous
#include <cuda_runtime.h>
#include <cuda_fp16.h>
#include <stdint.h>
#include <math.h>

// ---------------------------------------------------------------------------
// Problem dims
// ---------------------------------------------------------------------------
#define B_SZ   16384
#define D_IN   1280
#define D_HID  512
#define D_OUT  229
#define K1     (7 * D_IN)    // 8960
#define K2     (7 * D_HID)   // 3584
#define N2PAD  256

// ---------------------------------------------------------------------------
// Scratch
// ---------------------------------------------------------------------------
static __device__ __half g_A1[(size_t)B_SZ * K1];
static __device__ __half g_W1[(size_t)D_HID * K1];
static __device__ float  g_h [(size_t)B_SZ * D_HID];
static __device__ __half g_A2[(size_t)B_SZ * K2];
static __device__ __half g_W2[(size_t)N2PAD * K2];
static __device__ int    g_ln_ctr[128];   // per row-block arrival counter (self-resetting)

// ---------------------------------------------------------------------------
// Closed-form uniform cubic B-spline bases — static indexing (spill-free, R9)
// ---------------------------------------------------------------------------
__device__ __forceinline__ void kan_bases(float x, float bs[6]) {
    const float s  = (x + 3.0f) * 1.5f;
    const float cf = floorf(s);
    const int   c  = (int)cf;
    const float u  = s - cf;
    const float u2 = u * u;
    const float u3 = u2 * u;
    const float om = 1.0f - u;
    const float seg0 = om * om * om * (1.0f / 6.0f);
    const float seg1 = (3.0f * u3 - 6.0f * u2 + 4.0f) * (1.0f / 6.0f);
    const float seg2 = (-3.0f * u3 + 3.0f * u2 + 3.0f * u + 1.0f) * (1.0f / 6.0f);
    const float seg3 = u3 * (1.0f / 6.0f);
#pragma unroll
    for (int j = 0; j < 6; ++j) {
        float v = 0.0f;
        v = (c == j    ) ? seg3 : v;
        v = (c == j + 1) ? seg2 : v;
        v = (c == j + 2) ? seg1 : v;
        v = (c == j + 3) ? seg0 : v;
        bs[j] = v;
    }
}

__device__ __forceinline__ float silu_f(float v) { return v / (1.0f + expf(-v)); }

// ---------------------------------------------------------------------------
// Merged prep kernel (R9 champion structure): expand1 + fusew1 + fusew2
// ---------------------------------------------------------------------------
#define E1_BLOCKS (B_SZ * (D_IN / 2) / 256)      // 40960
#define F1_BLOCKS (D_HID * D_IN / 256)            // 2560
#define F2_BLOCKS (N2PAD * D_HID / 256)           // 512
#define PREP_BLOCKS (E1_BLOCKS + F1_BLOCKS + F2_BLOCKS)

__global__ __launch_bounds__(256) void prep_kernel(
    const float* __restrict__ x,
    const float* __restrict__ bw1, const float* __restrict__ sw1,
    const float* __restrict__ sc1,
    const float* __restrict__ bw2, const float* __restrict__ sw2,
    const float* __restrict__ sc2)
{
    const int blk = blockIdx.x;
    if (blk < E1_BLOCKS) {
        int idx = blk * 256 + threadIdx.x;
        int b  = idx / (D_IN / 2);
        int i2 = (idx - b * (D_IN / 2)) * 2;
        float2 v = *reinterpret_cast<const float2*>(x + (size_t)b * D_IN + i2);
        float bs0[6], bs1[6];
        kan_bases(v.x, bs0);
        kan_bases(v.y, bs1);
        size_t base = (size_t)b * K1 + i2;
        *reinterpret_cast<__half2*>(&g_A1[base]) =
            __floats2half2_rn(silu_f(v.x), silu_f(v.y));
#pragma unroll
        for (int j = 0; j < 6; ++j)
            *reinterpret_cast<__half2*>(&g_A1[base + (size_t)(j + 1) * D_IN]) =
                __floats2half2_rn(bs0[j], bs1[j]);
    } else if (blk < E1_BLOCKS + F1_BLOCKS) {
        int idx = (blk - E1_BLOCKS) * 256 + threadIdx.x;
        int o = idx / D_IN;
        int i = idx - o * D_IN;
        size_t base = (size_t)o * K1 + i;
        g_W1[base] = __float2half(bw1[idx]);
        float s = sc1[idx];
#pragma unroll
        for (int j = 0; j < 6; ++j)
            g_W1[base + (size_t)(j + 1) * D_IN] =
                __float2half(sw1[(size_t)idx * 6 + j] * s);
    } else {
        int idx = (blk - E1_BLOCKS - F1_BLOCKS) * 256 + threadIdx.x;
        int o = idx / D_HID;
        int c = idx - o * D_HID;
        size_t base = (size_t)o * K2 + c;
        if (o < D_OUT) {
            size_t widx = (size_t)o * D_HID + c;
            g_W2[base] = __float2half(bw2[widx]);
            float s = sc2[widx];
#pragma unroll
            for (int j = 0; j < 6; ++j)
                g_W2[base + (size_t)(j + 1) * D_HID] =
                    __float2half(sw2[widx * 6 + j] * s);
        } else {
            g_W2[base] = __float2half(0.0f);
#pragma unroll
            for (int j = 0; j < 6; ++j)
                g_W2[base + (size_t)(j + 1) * D_HID] = __float2half(0.0f);
        }
    }
}

// ---------------------------------------------------------------------------
// HMMA GEMM (frozen R9 mainloop — at the mma.sync instruction ceiling):
// Block 128x128x64, 512 threads (16 warps = 4M x 4N), warp tile 32x32.
// 32 warps/SM at 2 CTAs/SM. 3-stage cp.async ring. 144B smem rows.
// L==1 additionally runs a FUSED LayerNorm+expansion for its 128-row block:
// the 4th-arriving CTA (of the 4 nb-CTAs per mb) performs LN for those rows
// (threadFenceReduction pattern). LN of wave-1 mbs overlaps wave-2 GEMM.
// ---------------------------------------------------------------------------
#define BM 128
#define BN 128
#define BK 64
#define ROWB 144u
#define STG_B (uint32_t)((BM + BN) * ROWB)   // 36864 B
#define NSTG 3

template <int L>
__global__ __launch_bounds__(512, 2) void gemm_hmma(
    float* __restrict__ Cparam,
    const float* __restrict__ gamma, const float* __restrict__ beta)
{
    constexpr int KK = (L == 1) ? K1 : K2;
    constexpr int NV = (L == 1) ? D_HID : D_OUT;
    constexpr int KT = KK / BK;

    const __half* __restrict__ A  = (L == 1) ? g_A1 : g_A2;
    const __half* __restrict__ Bw = (L == 1) ? g_W1 : g_W2;
    float* __restrict__ C         = (L == 1) ? g_h  : Cparam;

    extern __shared__ __half smh[];
    const uint32_t sbase = (uint32_t)__cvta_generic_to_shared(smh);

    const int tid  = threadIdx.x;
    const int warp = tid >> 5;
    const int lane = tid & 31;
    const int wm = (warp & 3) * 32;
    const int wn = (warp >> 2) * 32;
    const int mb = blockIdx.y;
    const int nb = blockIdx.x;

    const __half* Abase = A  + (size_t)(mb * BM) * KK;
    const __half* Bbase = Bw + (size_t)(nb * BN) * KK;

    auto issue = [&](int kt) {
        const uint32_t sb = sbase + (uint32_t)(kt % NSTG) * STG_B;
#pragma unroll
        for (int i = 0; i < 2; ++i) {
            const int idx = tid + i * 512;
            const int r = idx >> 3, c = idx & 7;
            const void* src = Abase + (size_t)r * KK + kt * BK + c * 8;
            const uint32_t dst = sb + (uint32_t)r * ROWB + (uint32_t)c * 16u;
            asm volatile("cp.async.cg.shared.global [%0], [%1], 16;"
                         :: "r"(dst), "l"(src));
        }
#pragma unroll
        for (int i = 0; i < 2; ++i) {
            const int idx = tid + i * 512;
            const int r = idx >> 3, c = idx & 7;
            const void* src = Bbase + (size_t)r * KK + kt * BK + c * 8;
            const uint32_t dst = sb + (uint32_t)BM * ROWB
                               + (uint32_t)r * ROWB + (uint32_t)c * 16u;
            asm volatile("cp.async.cg.shared.global [%0], [%1], 16;"
                         :: "r"(dst), "l"(src));
        }
        asm volatile("cp.async.commit_group;" ::: "memory");
    };

    float acc[2][4][4] = {};

    issue(0); issue(1);

    const int lrow = lane & 15;
    const int lcb  = (lane >> 4) * 8;

#pragma unroll 1
    for (int kt = 0; kt < KT; ++kt) {
        if (kt + 1 < KT) asm volatile("cp.async.wait_group 1;" ::: "memory");
        else             asm volatile("cp.async.wait_group 0;" ::: "memory");
        __syncthreads();
        if (kt + 2 < KT) issue(kt + 2);

        const uint32_t sb = sbase + (uint32_t)(kt % NSTG) * STG_B;
#pragma unroll
        for (int ks = 0; ks < 4; ++ks) {
            uint32_t a[2][4];
            uint32_t bq[2][4];
#pragma unroll
            for (int mt = 0; mt < 2; ++mt) {
                const uint32_t addr = sb + (uint32_t)(wm + mt * 16 + lrow) * ROWB
                                    + (uint32_t)(ks * 16 + lcb) * 2u;
                asm volatile("ldmatrix.sync.aligned.m8n8.x4.shared.b16 {%0,%1,%2,%3}, [%4];"
                             : "=r"(a[mt][0]), "=r"(a[mt][1]), "=r"(a[mt][2]), "=r"(a[mt][3])
                             : "r"(addr));
            }
#pragma unroll
            for (int np = 0; np < 2; ++np) {
                const uint32_t addr = sb + (uint32_t)BM * ROWB
                                    + (uint32_t)(wn + np * 16 + lrow) * ROWB
                                    + (uint32_t)(ks * 16 + lcb) * 2u;
                asm volatile("ldmatrix.sync.aligned.m8n8.x4.shared.b16 {%0,%1,%2,%3}, [%4];"
                             : "=r"(bq[np][0]), "=r"(bq[np][1]), "=r"(bq[np][2]), "=r"(bq[np][3])
                             : "r"(addr));
            }
#pragma unroll
            for (int mt = 0; mt < 2; ++mt) {
#pragma unroll
                for (int nt = 0; nt < 4; ++nt) {
                    const int np = nt >> 1, pp = nt & 1;
                    asm volatile(
                        "mma.sync.aligned.m16n8k16.row.col.f32.f16.f16.f32 "
                        "{%0,%1,%2,%3}, {%4,%5,%6,%7}, {%8,%9}, {%0,%1,%2,%3};"
                        : "+f"(acc[mt][nt][0]), "+f"(acc[mt][nt][1]),
                          "+f"(acc[mt][nt][2]), "+f"(acc[mt][nt][3])
                        : "r"(a[mt][0]), "r"(a[mt][1]), "r"(a[mt][2]), "r"(a[mt][3]),
                          "r"(bq[np][pp]), "r"(bq[np][pp + 2]));
                }
            }
        }
    }

    // ---- epilogue: write C ----
    const int gr = lane >> 2;
    const int gc = (lane & 3) * 2;
#pragma unroll
    for (int mt = 0; mt < 2; ++mt) {
#pragma unroll
        for (int nt = 0; nt < 4; ++nt) {
            const int row = mb * BM + wm + mt * 16 + gr;
            const int col = nb * BN + wn + nt * 8 + gc;
            float* cp = C + (size_t)row * NV;
            if (NV % BN == 0) {
                cp[col]     = acc[mt][nt][0];
                cp[col + 1] = acc[mt][nt][1];
                cp += (size_t)8 * NV;
                cp[col]     = acc[mt][nt][2];
                cp[col + 1] = acc[mt][nt][3];
            } else {
                if (col < NV)     cp[col]     = acc[mt][nt][0];
                if (col + 1 < NV) cp[col + 1] = acc[mt][nt][1];
                cp += (size_t)8 * NV;
                if (col < NV)     cp[col]     = acc[mt][nt][2];
                if (col + 1 < NV) cp[col + 1] = acc[mt][nt][3];
            }
        }
    }

    // ---- fused LayerNorm + expansion (layer 1 only) ----
    if (L == 1) {
        __threadfence();                       // release this CTA's g_h tile
        __shared__ int s_do;
        __syncthreads();
        if (tid == 0) {
            int v = atomicAdd(&g_ln_ctr[mb], 1);
            s_do = (v == 3) ? 1 : 0;
            if (v == 3) g_ln_ctr[mb] = 0;      // self-reset for graph replay
        }
        __syncthreads();
        if (s_do) {
            __threadfence();                   // acquire peers' g_h tiles
            const int c0 = lane * 16;
            // warp w handles rows [mb*128 + w*8, +8)
#pragma unroll 1
            for (int i = 0; i < 8; ++i) {
                const int row = mb * BM + warp * 8 + i;
                const float* hr = g_h + (size_t)row * D_HID + c0;
                float4 tv[4];
                float s = 0.0f, q2 = 0.0f;
#pragma unroll
                for (int q = 0; q < 4; ++q) {
                    tv[q] = *reinterpret_cast<const float4*>(hr + q * 4);
                    s  += tv[q].x + tv[q].y + tv[q].z + tv[q].w;
                    q2 += tv[q].x * tv[q].x + tv[q].y * tv[q].y
                        + tv[q].z * tv[q].z + tv[q].w * tv[q].w;
                }
#pragma unroll
                for (int o = 16; o; o >>= 1) {
                    s  += __shfl_xor_sync(0xffffffffu, s, o);
                    q2 += __shfl_xor_sync(0xffffffffu, q2, o);
                }
                const float mean = s * (1.0f / (float)D_HID);
                const float var  = q2 * (1.0f / (float)D_HID) - mean * mean;
                const float inv  = rsqrtf(var + 1e-5f);

                __half* dst = g_A2 + (size_t)row * K2 + c0;
#pragma unroll
                for (int q = 0; q < 4; ++q) {
                    float4 g4 = *reinterpret_cast<const float4*>(gamma + c0 + q * 4);
                    float4 b4 = *reinterpret_cast<const float4*>(beta  + c0 + q * 4);
#pragma unroll
                    for (int p = 0; p < 2; ++p) {
                        const float v0 = (p == 0) ? tv[q].x : tv[q].z;
                        const float v1 = (p == 0) ? tv[q].y : tv[q].w;
                        const float g0 = (p == 0) ? g4.x : g4.z;
                        const float g1 = (p == 0) ? g4.y : g4.w;
                        const float e0 = (p == 0) ? b4.x : b4.z;
                        const float e1 = (p == 0) ? b4.y : b4.w;
                        const float y0 = (v0 - mean) * inv * g0 + e0;
                        const float y1 = (v1 - mean) * inv * g1 + e1;
                        float bs0[6], bs1[6];
                        kan_bases(y0, bs0);
                        kan_bases(y1, bs1);
                        const int cc = q * 4 + p * 2;
                        *reinterpret_cast<__half2*>(dst + cc) =
                            __floats2half2_rn(silu_f(y0), silu_f(y1));
#pragma unroll
                        for (int j = 0; j < 6; ++j)
                            *reinterpret_cast<__half2*>(dst + (size_t)(j + 1) * D_HID + cc) =
                                __floats2half2_rn(bs0[j], bs1[j]);
                    }
                }
            }
        }
    }
}

// ---------------------------------------------------------------------------
// Launch
// ---------------------------------------------------------------------------
#define GEMM_SMEM (NSTG * (int)STG_B)   // 110592 B

extern "C" void kernel_launch(void* const* d_in, const int* in_sizes, int n_in,
                              void* d_out, int out_size) {
    (void)in_sizes; (void)n_in; (void)out_size;
    const float* x   = (const float*)d_in[0];
    const float* bw1 = (const float*)d_in[1];
    const float* sw1 = (const float*)d_in[2];
    const float* sc1 = (const float*)d_in[3];
    const float* ga  = (const float*)d_in[4];
    const float* be  = (const float*)d_in[5];
    const float* bw2 = (const float*)d_in[6];
    const float* sw2 = (const float*)d_in[7];
    const float* sc2 = (const float*)d_in[8];
    float* out = (float*)d_out;

    cudaFuncSetAttribute(gemm_hmma<1>,
                         cudaFuncAttributeMaxDynamicSharedMemorySize, GEMM_SMEM);
    cudaFuncSetAttribute(gemm_hmma<2>,
                         cudaFuncAttributeMaxDynamicSharedMemorySize, GEMM_SMEM);

    // One merged prep launch: expand1 + fusew1 + fusew2
    prep_kernel<<<PREP_BLOCKS, 256>>>(x, bw1, sw1, sc1, bw2, sw2, sc2);

    // GEMM1 (+ fused LayerNorm/expansion): 512 CTAs (4 x 128)
    gemm_hmma<1><<<dim3(4, 128), 512, GEMM_SMEM>>>(nullptr, ga, be);

    // GEMM2: 256 CTAs (2 x 128)
    gemm_hmma<2><<<dim3(2, 128), 512, GEMM_SMEM>>>(out, nullptr, nullptr);
}

// round 13
// speedup vs baseline: 1.2076x; 1.1161x over previous
#include <cuda_runtime.h>
#include <cuda_fp16.h>
#include <stdint.h>
#include <math.h>

// ---------------------------------------------------------------------------
// Problem dims
// ---------------------------------------------------------------------------
#define B_SZ   16384
#define D_IN   1280
#define D_HID  512
#define D_OUT  229
#define K1     (7 * D_IN)    // 8960
#define K2     (7 * D_HID)   // 3584
#define N2PAD  256

// ---------------------------------------------------------------------------
// Scratch
// ---------------------------------------------------------------------------
static __device__ __half g_A1[(size_t)B_SZ * K1];
static __device__ __half g_W1[(size_t)D_HID * K1];
static __device__ float  g_h [(size_t)B_SZ * D_HID];
static __device__ __half g_A2[(size_t)B_SZ * K2];
static __device__ __half g_W2[(size_t)N2PAD * K2];
static __device__ int    g_ln_ctr[128];   // per row-block arrival counter (zeroed by prep)

// ---------------------------------------------------------------------------
// Closed-form uniform cubic B-spline bases — static indexing (spill-free, R9)
// ---------------------------------------------------------------------------
__device__ __forceinline__ void kan_bases(float x, float bs[6]) {
    const float s  = (x + 3.0f) * 1.5f;
    const float cf = floorf(s);
    const int   c  = (int)cf;
    const float u  = s - cf;
    const float u2 = u * u;
    const float u3 = u2 * u;
    const float om = 1.0f - u;
    const float seg0 = om * om * om * (1.0f / 6.0f);
    const float seg1 = (3.0f * u3 - 6.0f * u2 + 4.0f) * (1.0f / 6.0f);
    const float seg2 = (-3.0f * u3 + 3.0f * u2 + 3.0f * u + 1.0f) * (1.0f / 6.0f);
    const float seg3 = u3 * (1.0f / 6.0f);
#pragma unroll
    for (int j = 0; j < 6; ++j) {
        float v = 0.0f;
        v = (c == j    ) ? seg3 : v;
        v = (c == j + 1) ? seg2 : v;
        v = (c == j + 2) ? seg1 : v;
        v = (c == j + 3) ? seg0 : v;
        bs[j] = v;
    }
}

__device__ __forceinline__ float silu_f(float v) { return v / (1.0f + expf(-v)); }

// ---------------------------------------------------------------------------
// Merged prep kernel (R9 structure): expand1 + fusew1 + fusew2.
// Block 0 additionally zeroes the LN arrival counters (before gemm1 runs).
// ---------------------------------------------------------------------------
#define E1_BLOCKS (B_SZ * (D_IN / 2) / 256)      // 40960
#define F1_BLOCKS (D_HID * D_IN / 256)            // 2560
#define F2_BLOCKS (N2PAD * D_HID / 256)           // 512
#define PREP_BLOCKS (E1_BLOCKS + F1_BLOCKS + F2_BLOCKS)

__global__ __launch_bounds__(256) void prep_kernel(
    const float* __restrict__ x,
    const float* __restrict__ bw1, const float* __restrict__ sw1,
    const float* __restrict__ sc1,
    const float* __restrict__ bw2, const float* __restrict__ sw2,
    const float* __restrict__ sc2)
{
    const int blk = blockIdx.x;
    if (blk == 0 && threadIdx.x < 128) g_ln_ctr[threadIdx.x] = 0;
    if (blk < E1_BLOCKS) {
        int idx = blk * 256 + threadIdx.x;
        int b  = idx / (D_IN / 2);
        int i2 = (idx - b * (D_IN / 2)) * 2;
        float2 v = *reinterpret_cast<const float2*>(x + (size_t)b * D_IN + i2);
        float bs0[6], bs1[6];
        kan_bases(v.x, bs0);
        kan_bases(v.y, bs1);
        size_t base = (size_t)b * K1 + i2;
        *reinterpret_cast<__half2*>(&g_A1[base]) =
            __floats2half2_rn(silu_f(v.x), silu_f(v.y));
#pragma unroll
        for (int j = 0; j < 6; ++j)
            *reinterpret_cast<__half2*>(&g_A1[base + (size_t)(j + 1) * D_IN]) =
                __floats2half2_rn(bs0[j], bs1[j]);
    } else if (blk < E1_BLOCKS + F1_BLOCKS) {
        int idx = (blk - E1_BLOCKS) * 256 + threadIdx.x;
        int o = idx / D_IN;
        int i = idx - o * D_IN;
        size_t base = (size_t)o * K1 + i;
        g_W1[base] = __float2half(bw1[idx]);
        float s = sc1[idx];
#pragma unroll
        for (int j = 0; j < 6; ++j)
            g_W1[base + (size_t)(j + 1) * D_IN] =
                __float2half(sw1[(size_t)idx * 6 + j] * s);
    } else {
        int idx = (blk - E1_BLOCKS - F1_BLOCKS) * 256 + threadIdx.x;
        int o = idx / D_HID;
        int c = idx - o * D_HID;
        size_t base = (size_t)o * K2 + c;
        if (o < D_OUT) {
            size_t widx = (size_t)o * D_HID + c;
            g_W2[base] = __float2half(bw2[widx]);
            float s = sc2[widx];
#pragma unroll
            for (int j = 0; j < 6; ++j)
                g_W2[base + (size_t)(j + 1) * D_HID] =
                    __float2half(sw2[widx * 6 + j] * s);
        } else {
            g_W2[base] = __float2half(0.0f);
#pragma unroll
            for (int j = 0; j < 6; ++j)
                g_W2[base + (size_t)(j + 1) * D_HID] = __float2half(0.0f);
        }
    }
}

// ---------------------------------------------------------------------------
// HMMA GEMM (frozen R9 mainloop — at the mma.sync instruction ceiling):
// Block 128x128x64, 512 threads (16 warps = 4M x 4N), warp tile 32x32.
// 32 warps/SM at 2 CTAs/SM. 3-stage cp.async ring. 144B smem rows.
//
// L==1 fused LayerNorm+expansion, ALL-CTA version (fixes R12's tail):
// each of the 4 nb-CTAs of an mb arrives on g_ln_ctr[mb], spins until all 4
// arrived (adjacent bids -> co-resident; in-order dispatch -> no deadlock),
// then normalizes ITS OWN 32-row slice. Same thread-parallelism as the
// standalone LN kernel, but the launch + gap disappear and wave-1 LN
// overlaps wave-2 GEMM.
// ---------------------------------------------------------------------------
#define BM 128
#define BN 128
#define BK 64
#define ROWB 144u
#define STG_B (uint32_t)((BM + BN) * ROWB)   // 36864 B
#define NSTG 3

template <int L>
__global__ __launch_bounds__(512, 2) void gemm_hmma(
    float* __restrict__ Cparam,
    const float* __restrict__ gamma, const float* __restrict__ beta)
{
    constexpr int KK = (L == 1) ? K1 : K2;
    constexpr int NV = (L == 1) ? D_HID : D_OUT;
    constexpr int KT = KK / BK;

    const __half* __restrict__ A  = (L == 1) ? g_A1 : g_A2;
    const __half* __restrict__ Bw = (L == 1) ? g_W1 : g_W2;
    float* __restrict__ C         = (L == 1) ? g_h  : Cparam;

    extern __shared__ __half smh[];
    const uint32_t sbase = (uint32_t)__cvta_generic_to_shared(smh);

    const int tid  = threadIdx.x;
    const int warp = tid >> 5;
    const int lane = tid & 31;
    const int wm = (warp & 3) * 32;
    const int wn = (warp >> 2) * 32;
    const int mb = blockIdx.y;
    const int nb = blockIdx.x;

    const __half* Abase = A  + (size_t)(mb * BM) * KK;
    const __half* Bbase = Bw + (size_t)(nb * BN) * KK;

    auto issue = [&](int kt) {
        const uint32_t sb = sbase + (uint32_t)(kt % NSTG) * STG_B;
#pragma unroll
        for (int i = 0; i < 2; ++i) {
            const int idx = tid + i * 512;
            const int r = idx >> 3, c = idx & 7;
            const void* src = Abase + (size_t)r * KK + kt * BK + c * 8;
            const uint32_t dst = sb + (uint32_t)r * ROWB + (uint32_t)c * 16u;
            asm volatile("cp.async.cg.shared.global [%0], [%1], 16;"
                         :: "r"(dst), "l"(src));
        }
#pragma unroll
        for (int i = 0; i < 2; ++i) {
            const int idx = tid + i * 512;
            const int r = idx >> 3, c = idx & 7;
            const void* src = Bbase + (size_t)r * KK + kt * BK + c * 8;
            const uint32_t dst = sb + (uint32_t)BM * ROWB
                               + (uint32_t)r * ROWB + (uint32_t)c * 16u;
            asm volatile("cp.async.cg.shared.global [%0], [%1], 16;"
                         :: "r"(dst), "l"(src));
        }
        asm volatile("cp.async.commit_group;" ::: "memory");
    };

    float acc[2][4][4] = {};

    issue(0); issue(1);

    const int lrow = lane & 15;
    const int lcb  = (lane >> 4) * 8;

#pragma unroll 1
    for (int kt = 0; kt < KT; ++kt) {
        if (kt + 1 < KT) asm volatile("cp.async.wait_group 1;" ::: "memory");
        else             asm volatile("cp.async.wait_group 0;" ::: "memory");
        __syncthreads();
        if (kt + 2 < KT) issue(kt + 2);

        const uint32_t sb = sbase + (uint32_t)(kt % NSTG) * STG_B;
#pragma unroll
        for (int ks = 0; ks < 4; ++ks) {
            uint32_t a[2][4];
            uint32_t bq[2][4];
#pragma unroll
            for (int mt = 0; mt < 2; ++mt) {
                const uint32_t addr = sb + (uint32_t)(wm + mt * 16 + lrow) * ROWB
                                    + (uint32_t)(ks * 16 + lcb) * 2u;
                asm volatile("ldmatrix.sync.aligned.m8n8.x4.shared.b16 {%0,%1,%2,%3}, [%4];"
                             : "=r"(a[mt][0]), "=r"(a[mt][1]), "=r"(a[mt][2]), "=r"(a[mt][3])
                             : "r"(addr));
            }
#pragma unroll
            for (int np = 0; np < 2; ++np) {
                const uint32_t addr = sb + (uint32_t)BM * ROWB
                                    + (uint32_t)(wn + np * 16 + lrow) * ROWB
                                    + (uint32_t)(ks * 16 + lcb) * 2u;
                asm volatile("ldmatrix.sync.aligned.m8n8.x4.shared.b16 {%0,%1,%2,%3}, [%4];"
                             : "=r"(bq[np][0]), "=r"(bq[np][1]), "=r"(bq[np][2]), "=r"(bq[np][3])
                             : "r"(addr));
            }
#pragma unroll
            for (int mt = 0; mt < 2; ++mt) {
#pragma unroll
                for (int nt = 0; nt < 4; ++nt) {
                    const int np = nt >> 1, pp = nt & 1;
                    asm volatile(
                        "mma.sync.aligned.m16n8k16.row.col.f32.f16.f16.f32 "
                        "{%0,%1,%2,%3}, {%4,%5,%6,%7}, {%8,%9}, {%0,%1,%2,%3};"
                        : "+f"(acc[mt][nt][0]), "+f"(acc[mt][nt][1]),
                          "+f"(acc[mt][nt][2]), "+f"(acc[mt][nt][3])
                        : "r"(a[mt][0]), "r"(a[mt][1]), "r"(a[mt][2]), "r"(a[mt][3]),
                          "r"(bq[np][pp]), "r"(bq[np][pp + 2]));
                }
            }
        }
    }

    // ---- epilogue: write C ----
    const int gr = lane >> 2;
    const int gc = (lane & 3) * 2;
#pragma unroll
    for (int mt = 0; mt < 2; ++mt) {
#pragma unroll
        for (int nt = 0; nt < 4; ++nt) {
            const int row = mb * BM + wm + mt * 16 + gr;
            const int col = nb * BN + wn + nt * 8 + gc;
            float* cp = C + (size_t)row * NV;
            if (NV % BN == 0) {
                cp[col]     = acc[mt][nt][0];
                cp[col + 1] = acc[mt][nt][1];
                cp += (size_t)8 * NV;
                cp[col]     = acc[mt][nt][2];
                cp[col + 1] = acc[mt][nt][3];
            } else {
                if (col < NV)     cp[col]     = acc[mt][nt][0];
                if (col + 1 < NV) cp[col + 1] = acc[mt][nt][1];
                cp += (size_t)8 * NV;
                if (col < NV)     cp[col]     = acc[mt][nt][2];
                if (col + 1 < NV) cp[col + 1] = acc[mt][nt][3];
            }
        }
    }

    // ---- fused LayerNorm + expansion (layer 1 only, all CTAs participate) ----
    if (L == 1) {
        __threadfence();                       // release this CTA's g_h tile
        if (tid == 0) {
            atomicAdd(&g_ln_ctr[mb], 1);
            // spin until all 4 CTAs of this mb have arrived
            for (;;) {
                int v;
                asm volatile("ld.global.cg.b32 %0, [%1];"
                             : "=r"(v) : "l"(&g_ln_ctr[mb]));
                if (v >= 4) break;
                __nanosleep(64);
            }
        }
        __syncthreads();
        __threadfence();                       // acquire peers' g_h tiles

        // This CTA handles rows [mb*128 + nb*32, +32): warp w -> 2 rows.
        const int c0 = lane * 16;
#pragma unroll 1
        for (int i = 0; i < 2; ++i) {
            const int row = mb * BM + nb * 32 + warp * 2 + i;
            const float* hr = g_h + (size_t)row * D_HID + c0;
            float4 tv[4];
            float s = 0.0f, q2 = 0.0f;
#pragma unroll
            for (int q = 0; q < 4; ++q) {
                tv[q] = __ldcg(reinterpret_cast<const float4*>(hr + q * 4));
                s  += tv[q].x + tv[q].y + tv[q].z + tv[q].w;
                q2 += tv[q].x * tv[q].x + tv[q].y * tv[q].y
                    + tv[q].z * tv[q].z + tv[q].w * tv[q].w;
            }
#pragma unroll
            for (int o = 16; o; o >>= 1) {
                s  += __shfl_xor_sync(0xffffffffu, s, o);
                q2 += __shfl_xor_sync(0xffffffffu, q2, o);
            }
            const float mean = s * (1.0f / (float)D_HID);
            const float var  = q2 * (1.0f / (float)D_HID) - mean * mean;
            const float inv  = rsqrtf(var + 1e-5f);

            __half* dst = g_A2 + (size_t)row * K2 + c0;
#pragma unroll
            for (int q = 0; q < 4; ++q) {
                float4 g4 = *reinterpret_cast<const float4*>(gamma + c0 + q * 4);
                float4 b4 = *reinterpret_cast<const float4*>(beta  + c0 + q * 4);
#pragma unroll
                for (int p = 0; p < 2; ++p) {
                    const float v0 = (p == 0) ? tv[q].x : tv[q].z;
                    const float v1 = (p == 0) ? tv[q].y : tv[q].w;
                    const float g0 = (p == 0) ? g4.x : g4.z;
                    const float g1 = (p == 0) ? g4.y : g4.w;
                    const float e0 = (p == 0) ? b4.x : b4.z;
                    const float e1 = (p == 0) ? b4.y : b4.w;
                    const float y0 = (v0 - mean) * inv * g0 + e0;
                    const float y1 = (v1 - mean) * inv * g1 + e1;
                    float bs0[6], bs1[6];
                    kan_bases(y0, bs0);
                    kan_bases(y1, bs1);
                    const int cc = q * 4 + p * 2;
                    *reinterpret_cast<__half2*>(dst + cc) =
                        __floats2half2_rn(silu_f(y0), silu_f(y1));
#pragma unroll
                    for (int j = 0; j < 6; ++j)
                        *reinterpret_cast<__half2*>(dst + (size_t)(j + 1) * D_HID + cc) =
                            __floats2half2_rn(bs0[j], bs1[j]);
                }
            }
        }
    }
}

// ---------------------------------------------------------------------------
// Launch
// ---------------------------------------------------------------------------
#define GEMM_SMEM (NSTG * (int)STG_B)   // 110592 B

extern "C" void kernel_launch(void* const* d_in, const int* in_sizes, int n_in,
                              void* d_out, int out_size) {
    (void)in_sizes; (void)n_in; (void)out_size;
    const float* x   = (const float*)d_in[0];
    const float* bw1 = (const float*)d_in[1];
    const float* sw1 = (const float*)d_in[2];
    const float* sc1 = (const float*)d_in[3];
    const float* ga  = (const float*)d_in[4];
    const float* be  = (const float*)d_in[5];
    const float* bw2 = (const float*)d_in[6];
    const float* sw2 = (const float*)d_in[7];
    const float* sc2 = (const float*)d_in[8];
    float* out = (float*)d_out;

    cudaFuncSetAttribute(gemm_hmma<1>,
                         cudaFuncAttributeMaxDynamicSharedMemorySize, GEMM_SMEM);
    cudaFuncSetAttribute(gemm_hmma<2>,
                         cudaFuncAttributeMaxDynamicSharedMemorySize, GEMM_SMEM);

    // Merged prep: expand1 + fusew1 + fusew2 (+ LN counter reset)
    prep_kernel<<<PREP_BLOCKS, 256>>>(x, bw1, sw1, sc1, bw2, sw2, sc2);

    // GEMM1 with fused LayerNorm/expansion: 512 CTAs (4 x 128)
    gemm_hmma<1><<<dim3(4, 128), 512, GEMM_SMEM>>>(nullptr, ga, be);

    // GEMM2: 256 CTAs (2 x 128)
    gemm_hmma<2><<<dim3(2, 128), 512, GEMM_SMEM>>>(out, nullptr, nullptr);
}

// round 14
// speedup vs baseline: 1.4084x; 1.1663x over previous
#include <cuda_runtime.h>
#include <cuda_fp16.h>
#include <stdint.h>
#include <math.h>

// ---------------------------------------------------------------------------
// Problem dims
// ---------------------------------------------------------------------------
#define B_SZ   16384
#define D_IN   1280
#define D_HID  512
#define D_OUT  229
#define K1     (7 * D_IN)    // 8960
#define K2     (7 * D_HID)   // 3584
#define N2PAD  256

// ---------------------------------------------------------------------------
// Scratch
// ---------------------------------------------------------------------------
static __device__ __half g_A1[(size_t)B_SZ * K1];
static __device__ __half g_W1[(size_t)D_HID * K1];
static __device__ float  g_h [(size_t)B_SZ * D_HID];
static __device__ __half g_A2[(size_t)B_SZ * K2];
static __device__ __half g_W2[(size_t)N2PAD * K2];

// ---------------------------------------------------------------------------
// Closed-form uniform cubic B-spline bases — static indexing (spill-free, R9)
// ---------------------------------------------------------------------------
__device__ __forceinline__ void kan_bases(float x, float bs[6]) {
    const float s  = (x + 3.0f) * 1.5f;
    const float cf = floorf(s);
    const int   c  = (int)cf;
    const float u  = s - cf;
    const float u2 = u * u;
    const float u3 = u2 * u;
    const float om = 1.0f - u;
    const float seg0 = om * om * om * (1.0f / 6.0f);
    const float seg1 = (3.0f * u3 - 6.0f * u2 + 4.0f) * (1.0f / 6.0f);
    const float seg2 = (-3.0f * u3 + 3.0f * u2 + 3.0f * u + 1.0f) * (1.0f / 6.0f);
    const float seg3 = u3 * (1.0f / 6.0f);
#pragma unroll
    for (int j = 0; j < 6; ++j) {
        float v = 0.0f;
        v = (c == j    ) ? seg3 : v;
        v = (c == j + 1) ? seg2 : v;
        v = (c == j + 2) ? seg1 : v;
        v = (c == j + 3) ? seg0 : v;
        bs[j] = v;
    }
}

// silu via MUFU exp (prep is alu/issue-bound; poly expf was pure overhead;
// ~2ulp error is far below the f16 quantization applied right after)
__device__ __forceinline__ float silu_f(float v) {
    return v / (1.0f + __expf(-v));
}

// ---------------------------------------------------------------------------
// Merged prep kernel (R9 structure): expand1 + fusew1 + fusew2.
// 32-bit half2-granular indexing (all buffers < 2^31 half2 elements).
// ---------------------------------------------------------------------------
#define E1_BLOCKS (B_SZ * (D_IN / 2) / 256)      // 40960
#define F1_BLOCKS (D_HID * D_IN / 256)            // 2560
#define F2_BLOCKS (N2PAD * D_HID / 256)           // 512
#define PREP_BLOCKS (E1_BLOCKS + F1_BLOCKS + F2_BLOCKS)

__global__ __launch_bounds__(256) void prep_kernel(
    const float* __restrict__ x,
    const float* __restrict__ bw1, const float* __restrict__ sw1,
    const float* __restrict__ sc1,
    const float* __restrict__ bw2, const float* __restrict__ sw2,
    const float* __restrict__ sc2)
{
    const int blk = blockIdx.x;
    if (blk < E1_BLOCKS) {
        // ---- expand1: 2 features per thread, __half2 stores ----
        uint32_t idx = (uint32_t)blk * 256u + threadIdx.x;
        uint32_t b  = idx / (D_IN / 2);
        uint32_t ih = idx - b * (D_IN / 2);              // half2 index within row
        float2 v = *reinterpret_cast<const float2*>(x + (size_t)b * D_IN + ih * 2u);
        float bs0[6], bs1[6];
        kan_bases(v.x, bs0);
        kan_bases(v.y, bs1);
        __half2* dst = reinterpret_cast<__half2*>(g_A1) + (b * (uint32_t)(K1 / 2) + ih);
        dst[0] = __floats2half2_rn(silu_f(v.x), silu_f(v.y));
#pragma unroll
        for (int j = 0; j < 6; ++j)
            dst[(uint32_t)(j + 1) * (D_IN / 2)] = __floats2half2_rn(bs0[j], bs1[j]);
    } else if (blk < E1_BLOCKS + F1_BLOCKS) {
        // ---- fusew1 ----
        uint32_t idx = (uint32_t)(blk - E1_BLOCKS) * 256u + threadIdx.x;
        uint32_t o = idx / D_IN;
        uint32_t i = idx - o * D_IN;
        uint32_t base = o * (uint32_t)K1 + i;
        g_W1[base] = __float2half(bw1[idx]);
        float s = sc1[idx];
#pragma unroll
        for (int j = 0; j < 6; ++j)
            g_W1[base + (uint32_t)(j + 1) * D_IN] =
                __float2half(sw1[(size_t)idx * 6 + j] * s);
    } else {
        // ---- fusew2 (zero-padded rows o >= D_OUT) ----
        uint32_t idx = (uint32_t)(blk - E1_BLOCKS - F1_BLOCKS) * 256u + threadIdx.x;
        uint32_t o = idx / D_HID;
        uint32_t c = idx - o * D_HID;
        uint32_t base = o * (uint32_t)K2 + c;
        if (o < D_OUT) {
            uint32_t widx = o * (uint32_t)D_HID + c;
            g_W2[base] = __float2half(bw2[widx]);
            float s = sc2[widx];
#pragma unroll
            for (int j = 0; j < 6; ++j)
                g_W2[base + (uint32_t)(j + 1) * D_HID] =
                    __float2half(sw2[(size_t)widx * 6 + j] * s);
        } else {
            g_W2[base] = __float2half(0.0f);
#pragma unroll
            for (int j = 0; j < 6; ++j)
                g_W2[base + (uint32_t)(j + 1) * D_HID] = __float2half(0.0f);
        }
    }
}

// ---------------------------------------------------------------------------
// LayerNorm + expansion (R9 champion structure): block per row
// ---------------------------------------------------------------------------
__global__ __launch_bounds__(256) void ln_expand2_kernel(
    const float* __restrict__ gamma, const float* __restrict__ beta)
{
    int row = blockIdx.x;
    int t = threadIdx.x;
    const float* hr = g_h + (size_t)row * D_HID;
    float2 v = *reinterpret_cast<const float2*>(hr + 2 * t);

    __shared__ float red[8];
    float s = v.x + v.y;
#pragma unroll
    for (int o = 16; o; o >>= 1) s += __shfl_down_sync(0xffffffffu, s, o);
    if ((t & 31) == 0) red[t >> 5] = s;
    __syncthreads();
    float tot = 0.0f;
#pragma unroll
    for (int i = 0; i < 8; ++i) tot += red[i];
    float mean = tot * (1.0f / (float)D_HID);
    __syncthreads();

    float d0 = v.x - mean, d1 = v.y - mean;
    float q = d0 * d0 + d1 * d1;
#pragma unroll
    for (int o = 16; o; o >>= 1) q += __shfl_down_sync(0xffffffffu, q, o);
    if ((t & 31) == 0) red[t >> 5] = q;
    __syncthreads();
    float qt = 0.0f;
#pragma unroll
    for (int i = 0; i < 8; ++i) qt += red[i];
    float inv = rsqrtf(qt * (1.0f / (float)D_HID) + 1e-5f);

    const int c = 2 * t;
    float y0 = d0 * inv * gamma[c]     + beta[c];
    float y1 = d1 * inv * gamma[c + 1] + beta[c + 1];
    float bs0[6], bs1[6];
    kan_bases(y0, bs0);
    kan_bases(y1, bs1);
    __half2* dst = reinterpret_cast<__half2*>(g_A2)
                 + ((uint32_t)row * (uint32_t)(K2 / 2) + (uint32_t)t);
    dst[0] = __floats2half2_rn(silu_f(y0), silu_f(y1));
#pragma unroll
    for (int j = 0; j < 6; ++j)
        dst[(uint32_t)(j + 1) * (D_HID / 2)] = __floats2half2_rn(bs0[j], bs1[j]);
}

// ---------------------------------------------------------------------------
// HMMA GEMM (frozen R9 config — at the mma.sync instruction ceiling):
// Block 128x128x64, 512 threads (16 warps = 4M x 4N), warp tile 32x32.
// 32 warps/SM at 2 CTAs/SM. 3-stage cp.async ring. 144B smem rows.
// ---------------------------------------------------------------------------
#define BM 128
#define BN 128
#define BK 64
#define ROWB 144u
#define STG_B (uint32_t)((BM + BN) * ROWB)   // 36864 B
#define NSTG 3

template <int L>
__global__ __launch_bounds__(512, 2) void gemm_hmma(float* __restrict__ Cparam) {
    constexpr int KK = (L == 1) ? K1 : K2;
    constexpr int NV = (L == 1) ? D_HID : D_OUT;
    constexpr int KT = KK / BK;

    const __half* __restrict__ A  = (L == 1) ? g_A1 : g_A2;
    const __half* __restrict__ Bw = (L == 1) ? g_W1 : g_W2;
    float* __restrict__ C         = (L == 1) ? g_h  : Cparam;

    extern __shared__ __half smh[];
    const uint32_t sbase = (uint32_t)__cvta_generic_to_shared(smh);

    const int tid  = threadIdx.x;
    const int warp = tid >> 5;
    const int lane = tid & 31;
    const int wm = (warp & 3) * 32;
    const int wn = (warp >> 2) * 32;
    const int mb = blockIdx.y;
    const int nb = blockIdx.x;

    const __half* Abase = A  + (size_t)(mb * BM) * KK;
    const __half* Bbase = Bw + (size_t)(nb * BN) * KK;

    auto issue = [&](int kt) {
        const uint32_t sb = sbase + (uint32_t)(kt % NSTG) * STG_B;
#pragma unroll
        for (int i = 0; i < 2; ++i) {
            const int idx = tid + i * 512;
            const int r = idx >> 3, c = idx & 7;
            const void* src = Abase + (size_t)r * KK + kt * BK + c * 8;
            const uint32_t dst = sb + (uint32_t)r * ROWB + (uint32_t)c * 16u;
            asm volatile("cp.async.cg.shared.global [%0], [%1], 16;"
                         :: "r"(dst), "l"(src));
        }
#pragma unroll
        for (int i = 0; i < 2; ++i) {
            const int idx = tid + i * 512;
            const int r = idx >> 3, c = idx & 7;
            const void* src = Bbase + (size_t)r * KK + kt * BK + c * 8;
            const uint32_t dst = sb + (uint32_t)BM * ROWB
                               + (uint32_t)r * ROWB + (uint32_t)c * 16u;
            asm volatile("cp.async.cg.shared.global [%0], [%1], 16;"
                         :: "r"(dst), "l"(src));
        }
        asm volatile("cp.async.commit_group;" ::: "memory");
    };

    float acc[2][4][4] = {};

    issue(0); issue(1);

    const int lrow = lane & 15;
    const int lcb  = (lane >> 4) * 8;

#pragma unroll 1
    for (int kt = 0; kt < KT; ++kt) {
        if (kt + 1 < KT) asm volatile("cp.async.wait_group 1;" ::: "memory");
        else             asm volatile("cp.async.wait_group 0;" ::: "memory");
        __syncthreads();
        if (kt + 2 < KT) issue(kt + 2);

        const uint32_t sb = sbase + (uint32_t)(kt % NSTG) * STG_B;
#pragma unroll
        for (int ks = 0; ks < 4; ++ks) {
            uint32_t a[2][4];
            uint32_t bq[2][4];
#pragma unroll
            for (int mt = 0; mt < 2; ++mt) {
                const uint32_t addr = sb + (uint32_t)(wm + mt * 16 + lrow) * ROWB
                                    + (uint32_t)(ks * 16 + lcb) * 2u;
                asm volatile("ldmatrix.sync.aligned.m8n8.x4.shared.b16 {%0,%1,%2,%3}, [%4];"
                             : "=r"(a[mt][0]), "=r"(a[mt][1]), "=r"(a[mt][2]), "=r"(a[mt][3])
                             : "r"(addr));
            }
#pragma unroll
            for (int np = 0; np < 2; ++np) {
                const uint32_t addr = sb + (uint32_t)BM * ROWB
                                    + (uint32_t)(wn + np * 16 + lrow) * ROWB
                                    + (uint32_t)(ks * 16 + lcb) * 2u;
                asm volatile("ldmatrix.sync.aligned.m8n8.x4.shared.b16 {%0,%1,%2,%3}, [%4];"
                             : "=r"(bq[np][0]), "=r"(bq[np][1]), "=r"(bq[np][2]), "=r"(bq[np][3])
                             : "r"(addr));
            }
#pragma unroll
            for (int mt = 0; mt < 2; ++mt) {
#pragma unroll
                for (int nt = 0; nt < 4; ++nt) {
                    const int np = nt >> 1, pp = nt & 1;
                    asm volatile(
                        "mma.sync.aligned.m16n8k16.row.col.f32.f16.f16.f32 "
                        "{%0,%1,%2,%3}, {%4,%5,%6,%7}, {%8,%9}, {%0,%1,%2,%3};"
                        : "+f"(acc[mt][nt][0]), "+f"(acc[mt][nt][1]),
                          "+f"(acc[mt][nt][2]), "+f"(acc[mt][nt][3])
                        : "r"(a[mt][0]), "r"(a[mt][1]), "r"(a[mt][2]), "r"(a[mt][3]),
                          "r"(bq[np][pp]), "r"(bq[np][pp + 2]));
                }
            }
        }
    }

    // ---- epilogue ----
    const int gr = lane >> 2;
    const int gc = (lane & 3) * 2;
#pragma unroll
    for (int mt = 0; mt < 2; ++mt) {
#pragma unroll
        for (int nt = 0; nt < 4; ++nt) {
            const int row = mb * BM + wm + mt * 16 + gr;
            const int col = nb * BN + wn + nt * 8 + gc;
            float* cp = C + (size_t)row * NV;
            if (NV % BN == 0) {
                cp[col]     = acc[mt][nt][0];
                cp[col + 1] = acc[mt][nt][1];
                cp += (size_t)8 * NV;
                cp[col]     = acc[mt][nt][2];
                cp[col + 1] = acc[mt][nt][3];
            } else {
                if (col < NV)     cp[col]     = acc[mt][nt][0];
                if (col + 1 < NV) cp[col + 1] = acc[mt][nt][1];
                cp += (size_t)8 * NV;
                if (col < NV)     cp[col]     = acc[mt][nt][2];
                if (col + 1 < NV) cp[col + 1] = acc[mt][nt][3];
            }
        }
    }
}

// ---------------------------------------------------------------------------
// Launch
// ---------------------------------------------------------------------------
#define GEMM_SMEM (NSTG * (int)STG_B)   // 110592 B

extern "C" void kernel_launch(void* const* d_in, const int* in_sizes, int n_in,
                              void* d_out, int out_size) {
    (void)in_sizes; (void)n_in; (void)out_size;
    const float* x   = (const float*)d_in[0];
    const float* bw1 = (const float*)d_in[1];
    const float* sw1 = (const float*)d_in[2];
    const float* sc1 = (const float*)d_in[3];
    const float* ga  = (const float*)d_in[4];
    const float* be  = (const float*)d_in[5];
    const float* bw2 = (const float*)d_in[6];
    const float* sw2 = (const float*)d_in[7];
    const float* sc2 = (const float*)d_in[8];
    float* out = (float*)d_out;

    cudaFuncSetAttribute(gemm_hmma<1>,
                         cudaFuncAttributeMaxDynamicSharedMemorySize, GEMM_SMEM);
    cudaFuncSetAttribute(gemm_hmma<2>,
                         cudaFuncAttributeMaxDynamicSharedMemorySize, GEMM_SMEM);

    // One merged prep launch: expand1 + fusew1 + fusew2
    prep_kernel<<<PREP_BLOCKS, 256>>>(x, bw1, sw1, sc1, bw2, sw2, sc2);

    // GEMM1: 512 CTAs (4 x 128)
    gemm_hmma<1><<<dim3(4, 128), 512, GEMM_SMEM>>>(nullptr);

    ln_expand2_kernel<<<B_SZ, 256>>>(ga, be);

    // GEMM2: 256 CTAs (2 x 128)
    gemm_hmma<2><<<dim3(2, 128), 512, GEMM_SMEM>>>(out);
}

// round 15
// speedup vs baseline: 1.4298x; 1.0152x over previous
#include <cuda_runtime.h>
#include <cuda_fp16.h>
#include <stdint.h>
#include <math.h>

// ---------------------------------------------------------------------------
// Problem dims
// ---------------------------------------------------------------------------
#define B_SZ   16384
#define D_IN   1280
#define D_HID  512
#define D_OUT  229
#define K1     (7 * D_IN)    // 8960
#define K2     (7 * D_HID)   // 3584
#define N2PAD  256

// ---------------------------------------------------------------------------
// Scratch
// ---------------------------------------------------------------------------
static __device__ __half g_A1[(size_t)B_SZ * K1];
static __device__ __half g_W1[(size_t)D_HID * K1];
static __device__ float  g_h [(size_t)B_SZ * D_HID];
static __device__ __half g_A2[(size_t)B_SZ * K2];
static __device__ __half g_W2[(size_t)N2PAD * K2];

// ---------------------------------------------------------------------------
// Closed-form uniform cubic B-spline bases — static indexing (spill-free, R9)
// ---------------------------------------------------------------------------
__device__ __forceinline__ void kan_bases(float x, float bs[6]) {
    const float s  = (x + 3.0f) * 1.5f;
    const float cf = floorf(s);
    const int   c  = (int)cf;
    const float u  = s - cf;
    const float u2 = u * u;
    const float u3 = u2 * u;
    const float om = 1.0f - u;
    const float seg0 = om * om * om * (1.0f / 6.0f);
    const float seg1 = (3.0f * u3 - 6.0f * u2 + 4.0f) * (1.0f / 6.0f);
    const float seg2 = (-3.0f * u3 + 3.0f * u2 + 3.0f * u + 1.0f) * (1.0f / 6.0f);
    const float seg3 = u3 * (1.0f / 6.0f);
#pragma unroll
    for (int j = 0; j < 6; ++j) {
        float v = 0.0f;
        v = (c == j    ) ? seg3 : v;
        v = (c == j + 1) ? seg2 : v;
        v = (c == j + 2) ? seg1 : v;
        v = (c == j + 3) ? seg0 : v;
        bs[j] = v;
    }
}

// silu via MUFU exp + fast divide (error ~1-2 ulp, far below the f16
// quantization applied immediately after)
__device__ __forceinline__ float silu_f(float v) {
    return __fdividef(v, 1.0f + __expf(-v));
}

__device__ __forceinline__ uint32_t pk2(float a, float b) {
    __half2 h = __floats2half2_rn(a, b);
    return *reinterpret_cast<uint32_t*>(&h);
}

// ---------------------------------------------------------------------------
// Merged prep kernel: expand1 (4 features/thread, uint2 stores) +
// fusew1 + fusew2 (R9 structure).
// ---------------------------------------------------------------------------
#define E1_BLOCKS (B_SZ * (D_IN / 4) / 256)      // 20480
#define F1_BLOCKS (D_HID * D_IN / 256)            // 2560
#define F2_BLOCKS (N2PAD * D_HID / 256)           // 512
#define PREP_BLOCKS (E1_BLOCKS + F1_BLOCKS + F2_BLOCKS)

__global__ __launch_bounds__(256) void prep_kernel(
    const float* __restrict__ x,
    const float* __restrict__ bw1, const float* __restrict__ sw1,
    const float* __restrict__ sc1,
    const float* __restrict__ bw2, const float* __restrict__ sw2,
    const float* __restrict__ sc2)
{
    const int blk = blockIdx.x;
    if (blk < E1_BLOCKS) {
        // ---- expand1: 4 consecutive features per thread, 8B stores ----
        uint32_t idx = (uint32_t)blk * 256u + threadIdx.x;   // over B_SZ * 320
        uint32_t b  = idx / (D_IN / 4);
        uint32_t i4 = (idx - b * (D_IN / 4)) * 4u;
        float4 v = *reinterpret_cast<const float4*>(x + (size_t)b * D_IN + i4);
        float bs0[6], bs1[6], bs2[6], bs3[6];
        kan_bases(v.x, bs0);
        kan_bases(v.y, bs1);
        kan_bases(v.z, bs2);
        kan_bases(v.w, bs3);
        __half* dstp = g_A1 + ((size_t)b * K1 + i4);
        uint2 r;
        r.x = pk2(silu_f(v.x), silu_f(v.y));
        r.y = pk2(silu_f(v.z), silu_f(v.w));
        *reinterpret_cast<uint2*>(dstp) = r;
#pragma unroll
        for (int j = 0; j < 6; ++j) {
            r.x = pk2(bs0[j], bs1[j]);
            r.y = pk2(bs2[j], bs3[j]);
            *reinterpret_cast<uint2*>(dstp + (uint32_t)(j + 1) * D_IN) = r;
        }
    } else if (blk < E1_BLOCKS + F1_BLOCKS) {
        // ---- fusew1 ----
        uint32_t idx = (uint32_t)(blk - E1_BLOCKS) * 256u + threadIdx.x;
        uint32_t o = idx / D_IN;
        uint32_t i = idx - o * D_IN;
        uint32_t base = o * (uint32_t)K1 + i;
        g_W1[base] = __float2half(bw1[idx]);
        float s = sc1[idx];
#pragma unroll
        for (int j = 0; j < 6; ++j)
            g_W1[base + (uint32_t)(j + 1) * D_IN] =
                __float2half(sw1[(size_t)idx * 6 + j] * s);
    } else {
        // ---- fusew2 (zero-padded rows o >= D_OUT) ----
        uint32_t idx = (uint32_t)(blk - E1_BLOCKS - F1_BLOCKS) * 256u + threadIdx.x;
        uint32_t o = idx / D_HID;
        uint32_t c = idx - o * D_HID;
        uint32_t base = o * (uint32_t)K2 + c;
        if (o < D_OUT) {
            uint32_t widx = o * (uint32_t)D_HID + c;
            g_W2[base] = __float2half(bw2[widx]);
            float s = sc2[widx];
#pragma unroll
            for (int j = 0; j < 6; ++j)
                g_W2[base + (uint32_t)(j + 1) * D_HID] =
                    __float2half(sw2[(size_t)widx * 6 + j] * s);
        } else {
            g_W2[base] = __float2half(0.0f);
#pragma unroll
            for (int j = 0; j < 6; ++j)
                g_W2[base + (uint32_t)(j + 1) * D_HID] = __float2half(0.0f);
        }
    }
}

// ---------------------------------------------------------------------------
// LayerNorm + expansion (R9 champion structure): block per row
// ---------------------------------------------------------------------------
__global__ __launch_bounds__(256) void ln_expand2_kernel(
    const float* __restrict__ gamma, const float* __restrict__ beta)
{
    int row = blockIdx.x;
    int t = threadIdx.x;
    const float* hr = g_h + (size_t)row * D_HID;
    float2 v = *reinterpret_cast<const float2*>(hr + 2 * t);

    __shared__ float red[8];
    float s = v.x + v.y;
#pragma unroll
    for (int o = 16; o; o >>= 1) s += __shfl_down_sync(0xffffffffu, s, o);
    if ((t & 31) == 0) red[t >> 5] = s;
    __syncthreads();
    float tot = 0.0f;
#pragma unroll
    for (int i = 0; i < 8; ++i) tot += red[i];
    float mean = tot * (1.0f / (float)D_HID);
    __syncthreads();

    float d0 = v.x - mean, d1 = v.y - mean;
    float q = d0 * d0 + d1 * d1;
#pragma unroll
    for (int o = 16; o; o >>= 1) q += __shfl_down_sync(0xffffffffu, q, o);
    if ((t & 31) == 0) red[t >> 5] = q;
    __syncthreads();
    float qt = 0.0f;
#pragma unroll
    for (int i = 0; i < 8; ++i) qt += red[i];
    float inv = rsqrtf(qt * (1.0f / (float)D_HID) + 1e-5f);

    const int c = 2 * t;
    float y0 = d0 * inv * gamma[c]     + beta[c];
    float y1 = d1 * inv * gamma[c + 1] + beta[c + 1];
    float bs0[6], bs1[6];
    kan_bases(y0, bs0);
    kan_bases(y1, bs1);
    __half2* dst = reinterpret_cast<__half2*>(g_A2)
                 + ((uint32_t)row * (uint32_t)(K2 / 2) + (uint32_t)t);
    dst[0] = __floats2half2_rn(silu_f(y0), silu_f(y1));
#pragma unroll
    for (int j = 0; j < 6; ++j)
        dst[(uint32_t)(j + 1) * (D_HID / 2)] = __floats2half2_rn(bs0[j], bs1[j]);
}

// ---------------------------------------------------------------------------
// HMMA GEMM (frozen R9 config — at the mma.sync instruction ceiling):
// Block 128x128x64, 512 threads (16 warps = 4M x 4N), warp tile 32x32.
// 32 warps/SM at 2 CTAs/SM. 3-stage cp.async ring. 144B smem rows.
// ---------------------------------------------------------------------------
#define BM 128
#define BN 128
#define BK 64
#define ROWB 144u
#define STG_B (uint32_t)((BM + BN) * ROWB)   // 36864 B
#define NSTG 3

template <int L>
__global__ __launch_bounds__(512, 2) void gemm_hmma(float* __restrict__ Cparam) {
    constexpr int KK = (L == 1) ? K1 : K2;
    constexpr int NV = (L == 1) ? D_HID : D_OUT;
    constexpr int KT = KK / BK;

    const __half* __restrict__ A  = (L == 1) ? g_A1 : g_A2;
    const __half* __restrict__ Bw = (L == 1) ? g_W1 : g_W2;
    float* __restrict__ C         = (L == 1) ? g_h  : Cparam;

    extern __shared__ __half smh[];
    const uint32_t sbase = (uint32_t)__cvta_generic_to_shared(smh);

    const int tid  = threadIdx.x;
    const int warp = tid >> 5;
    const int lane = tid & 31;
    const int wm = (warp & 3) * 32;
    const int wn = (warp >> 2) * 32;
    const int mb = blockIdx.y;
    const int nb = blockIdx.x;

    const __half* Abase = A  + (size_t)(mb * BM) * KK;
    const __half* Bbase = Bw + (size_t)(nb * BN) * KK;

    auto issue = [&](int kt) {
        const uint32_t sb = sbase + (uint32_t)(kt % NSTG) * STG_B;
#pragma unroll
        for (int i = 0; i < 2; ++i) {
            const int idx = tid + i * 512;
            const int r = idx >> 3, c = idx & 7;
            const void* src = Abase + (size_t)r * KK + kt * BK + c * 8;
            const uint32_t dst = sb + (uint32_t)r * ROWB + (uint32_t)c * 16u;
            asm volatile("cp.async.cg.shared.global [%0], [%1], 16;"
                         :: "r"(dst), "l"(src));
        }
#pragma unroll
        for (int i = 0; i < 2; ++i) {
            const int idx = tid + i * 512;
            const int r = idx >> 3, c = idx & 7;
            const void* src = Bbase + (size_t)r * KK + kt * BK + c * 8;
            const uint32_t dst = sb + (uint32_t)BM * ROWB
                               + (uint32_t)r * ROWB + (uint32_t)c * 16u;
            asm volatile("cp.async.cg.shared.global [%0], [%1], 16;"
                         :: "r"(dst), "l"(src));
        }
        asm volatile("cp.async.commit_group;" ::: "memory");
    };

    float acc[2][4][4] = {};

    issue(0); issue(1);

    const int lrow = lane & 15;
    const int lcb  = (lane >> 4) * 8;

#pragma unroll 1
    for (int kt = 0; kt < KT; ++kt) {
        if (kt + 1 < KT) asm volatile("cp.async.wait_group 1;" ::: "memory");
        else             asm volatile("cp.async.wait_group 0;" ::: "memory");
        __syncthreads();
        if (kt + 2 < KT) issue(kt + 2);

        const uint32_t sb = sbase + (uint32_t)(kt % NSTG) * STG_B;
#pragma unroll
        for (int ks = 0; ks < 4; ++ks) {
            uint32_t a[2][4];
            uint32_t bq[2][4];
#pragma unroll
            for (int mt = 0; mt < 2; ++mt) {
                const uint32_t addr = sb + (uint32_t)(wm + mt * 16 + lrow) * ROWB
                                    + (uint32_t)(ks * 16 + lcb) * 2u;
                asm volatile("ldmatrix.sync.aligned.m8n8.x4.shared.b16 {%0,%1,%2,%3}, [%4];"
                             : "=r"(a[mt][0]), "=r"(a[mt][1]), "=r"(a[mt][2]), "=r"(a[mt][3])
                             : "r"(addr));
            }
#pragma unroll
            for (int np = 0; np < 2; ++np) {
                const uint32_t addr = sb + (uint32_t)BM * ROWB
                                    + (uint32_t)(wn + np * 16 + lrow) * ROWB
                                    + (uint32_t)(ks * 16 + lcb) * 2u;
                asm volatile("ldmatrix.sync.aligned.m8n8.x4.shared.b16 {%0,%1,%2,%3}, [%4];"
                             : "=r"(bq[np][0]), "=r"(bq[np][1]), "=r"(bq[np][2]), "=r"(bq[np][3])
                             : "r"(addr));
            }
#pragma unroll
            for (int mt = 0; mt < 2; ++mt) {
#pragma unroll
                for (int nt = 0; nt < 4; ++nt) {
                    const int np = nt >> 1, pp = nt & 1;
                    asm volatile(
                        "mma.sync.aligned.m16n8k16.row.col.f32.f16.f16.f32 "
                        "{%0,%1,%2,%3}, {%4,%5,%6,%7}, {%8,%9}, {%0,%1,%2,%3};"
                        : "+f"(acc[mt][nt][0]), "+f"(acc[mt][nt][1]),
                          "+f"(acc[mt][nt][2]), "+f"(acc[mt][nt][3])
                        : "r"(a[mt][0]), "r"(a[mt][1]), "r"(a[mt][2]), "r"(a[mt][3]),
                          "r"(bq[np][pp]), "r"(bq[np][pp + 2]));
                }
            }
        }
    }

    // ---- epilogue ----
    const int gr = lane >> 2;
    const int gc = (lane & 3) * 2;
#pragma unroll
    for (int mt = 0; mt < 2; ++mt) {
#pragma unroll
        for (int nt = 0; nt < 4; ++nt) {
            const int row = mb * BM + wm + mt * 16 + gr;
            const int col = nb * BN + wn + nt * 8 + gc;
            float* cp = C + (size_t)row * NV;
            if (NV % BN == 0) {
                cp[col]     = acc[mt][nt][0];
                cp[col + 1] = acc[mt][nt][1];
                cp += (size_t)8 * NV;
                cp[col]     = acc[mt][nt][2];
                cp[col + 1] = acc[mt][nt][3];
            } else {
                if (col < NV)     cp[col]     = acc[mt][nt][0];
                if (col + 1 < NV) cp[col + 1] = acc[mt][nt][1];
                cp += (size_t)8 * NV;
                if (col < NV)     cp[col]     = acc[mt][nt][2];
                if (col + 1 < NV) cp[col + 1] = acc[mt][nt][3];
            }
        }
    }
}

// ---------------------------------------------------------------------------
// Launch
// ---------------------------------------------------------------------------
#define GEMM_SMEM (NSTG * (int)STG_B)   // 110592 B

extern "C" void kernel_launch(void* const* d_in, const int* in_sizes, int n_in,
                              void* d_out, int out_size) {
    (void)in_sizes; (void)n_in; (void)out_size;
    const float* x   = (const float*)d_in[0];
    const float* bw1 = (const float*)d_in[1];
    const float* sw1 = (const float*)d_in[2];
    const float* sc1 = (const float*)d_in[3];
    const float* ga  = (const float*)d_in[4];
    const float* be  = (const float*)d_in[5];
    const float* bw2 = (const float*)d_in[6];
    const float* sw2 = (const float*)d_in[7];
    const float* sc2 = (const float*)d_in[8];
    float* out = (float*)d_out;

    cudaFuncSetAttribute(gemm_hmma<1>,
                         cudaFuncAttributeMaxDynamicSharedMemorySize, GEMM_SMEM);
    cudaFuncSetAttribute(gemm_hmma<2>,
                         cudaFuncAttributeMaxDynamicSharedMemorySize, GEMM_SMEM);

    // One merged prep launch: expand1 + fusew1 + fusew2
    prep_kernel<<<PREP_BLOCKS, 256>>>(x, bw1, sw1, sc1, bw2, sw2, sc2);

    // GEMM1: 512 CTAs (4 x 128)
    gemm_hmma<1><<<dim3(4, 128), 512, GEMM_SMEM>>>(nullptr);

    ln_expand2_kernel<<<B_SZ, 256>>>(ga, be);

    // GEMM2: 256 CTAs (2 x 128)
    gemm_hmma<2><<<dim3(2, 128), 512, GEMM_SMEM>>>(out);
}

// round 16
// speedup vs baseline: 1.4454x; 1.0109x over previous
#include <cuda_runtime.h>
#include <cuda_fp16.h>
#include <stdint.h>
#include <math.h>

// ---------------------------------------------------------------------------
// Problem dims
// ---------------------------------------------------------------------------
#define B_SZ   16384
#define D_IN   1280
#define D_HID  512
#define D_OUT  229
#define K1     (7 * D_IN)    // 8960
#define K2     (7 * D_HID)   // 3584
#define N2PAD  256

// ---------------------------------------------------------------------------
// Scratch
// ---------------------------------------------------------------------------
static __device__ __half g_A1[(size_t)B_SZ * K1];
static __device__ __half g_W1[(size_t)D_HID * K1];
static __device__ float  g_h [(size_t)B_SZ * D_HID];
static __device__ __half g_A2[(size_t)B_SZ * K2];
static __device__ __half g_W2[(size_t)N2PAD * K2];

// ---------------------------------------------------------------------------
// Closed-form uniform cubic B-spline bases — static indexing (spill-free, R9)
// ---------------------------------------------------------------------------
__device__ __forceinline__ void kan_bases(float x, float bs[6]) {
    const float s  = (x + 3.0f) * 1.5f;
    const float cf = floorf(s);
    const int   c  = (int)cf;
    const float u  = s - cf;
    const float u2 = u * u;
    const float u3 = u2 * u;
    const float om = 1.0f - u;
    const float seg0 = om * om * om * (1.0f / 6.0f);
    const float seg1 = (3.0f * u3 - 6.0f * u2 + 4.0f) * (1.0f / 6.0f);
    const float seg2 = (-3.0f * u3 + 3.0f * u2 + 3.0f * u + 1.0f) * (1.0f / 6.0f);
    const float seg3 = u3 * (1.0f / 6.0f);
#pragma unroll
    for (int j = 0; j < 6; ++j) {
        float v = 0.0f;
        v = (c == j    ) ? seg3 : v;
        v = (c == j + 1) ? seg2 : v;
        v = (c == j + 2) ? seg1 : v;
        v = (c == j + 3) ? seg0 : v;
        bs[j] = v;
    }
}

// silu via MUFU exp + fast divide (error ~1-2 ulp, far below the f16
// quantization applied immediately after)
__device__ __forceinline__ float silu_f(float v) {
    return __fdividef(v, 1.0f + __expf(-v));
}

__device__ __forceinline__ uint32_t pk2(float a, float b) {
    __half2 h = __floats2half2_rn(a, b);
    return *reinterpret_cast<uint32_t*>(&h);
}

// ---------------------------------------------------------------------------
// Merged prep kernel (R15 champion): expand1 (4 features/thread, uint2 stores)
// + fusew1 + fusew2.
// ---------------------------------------------------------------------------
#define E1_BLOCKS (B_SZ * (D_IN / 4) / 256)      // 20480
#define F1_BLOCKS (D_HID * D_IN / 256)            // 2560
#define F2_BLOCKS (N2PAD * D_HID / 256)           // 512
#define PREP_BLOCKS (E1_BLOCKS + F1_BLOCKS + F2_BLOCKS)

__global__ __launch_bounds__(256) void prep_kernel(
    const float* __restrict__ x,
    const float* __restrict__ bw1, const float* __restrict__ sw1,
    const float* __restrict__ sc1,
    const float* __restrict__ bw2, const float* __restrict__ sw2,
    const float* __restrict__ sc2)
{
    const int blk = blockIdx.x;
    if (blk < E1_BLOCKS) {
        uint32_t idx = (uint32_t)blk * 256u + threadIdx.x;   // over B_SZ * 320
        uint32_t b  = idx / (D_IN / 4);
        uint32_t i4 = (idx - b * (D_IN / 4)) * 4u;
        float4 v = *reinterpret_cast<const float4*>(x + (size_t)b * D_IN + i4);
        float bs0[6], bs1[6], bs2[6], bs3[6];
        kan_bases(v.x, bs0);
        kan_bases(v.y, bs1);
        kan_bases(v.z, bs2);
        kan_bases(v.w, bs3);
        __half* dstp = g_A1 + ((size_t)b * K1 + i4);
        uint2 r;
        r.x = pk2(silu_f(v.x), silu_f(v.y));
        r.y = pk2(silu_f(v.z), silu_f(v.w));
        *reinterpret_cast<uint2*>(dstp) = r;
#pragma unroll
        for (int j = 0; j < 6; ++j) {
            r.x = pk2(bs0[j], bs1[j]);
            r.y = pk2(bs2[j], bs3[j]);
            *reinterpret_cast<uint2*>(dstp + (uint32_t)(j + 1) * D_IN) = r;
        }
    } else if (blk < E1_BLOCKS + F1_BLOCKS) {
        uint32_t idx = (uint32_t)(blk - E1_BLOCKS) * 256u + threadIdx.x;
        uint32_t o = idx / D_IN;
        uint32_t i = idx - o * D_IN;
        uint32_t base = o * (uint32_t)K1 + i;
        g_W1[base] = __float2half(bw1[idx]);
        float s = sc1[idx];
#pragma unroll
        for (int j = 0; j < 6; ++j)
            g_W1[base + (uint32_t)(j + 1) * D_IN] =
                __float2half(sw1[(size_t)idx * 6 + j] * s);
    } else {
        uint32_t idx = (uint32_t)(blk - E1_BLOCKS - F1_BLOCKS) * 256u + threadIdx.x;
        uint32_t o = idx / D_HID;
        uint32_t c = idx - o * D_HID;
        uint32_t base = o * (uint32_t)K2 + c;
        if (o < D_OUT) {
            uint32_t widx = o * (uint32_t)D_HID + c;
            g_W2[base] = __float2half(bw2[widx]);
            float s = sc2[widx];
#pragma unroll
            for (int j = 0; j < 6; ++j)
                g_W2[base + (uint32_t)(j + 1) * D_HID] =
                    __float2half(sw2[(size_t)widx * 6 + j] * s);
        } else {
            g_W2[base] = __float2half(0.0f);
#pragma unroll
            for (int j = 0; j < 6; ++j)
                g_W2[base + (uint32_t)(j + 1) * D_HID] = __float2half(0.0f);
        }
    }
}

// ---------------------------------------------------------------------------
// LayerNorm + expansion, R15-style: 128 threads per row, 4 cols per thread,
// float4 load, ONE fused sum+sumsq reduction (1 __syncthreads), uint2 stores.
// ---------------------------------------------------------------------------
__global__ __launch_bounds__(128) void ln_expand2_kernel(
    const float* __restrict__ gamma, const float* __restrict__ beta)
{
    const int row = blockIdx.x;
    const int t   = threadIdx.x;
    const int c4  = t * 4;

    float4 v = *reinterpret_cast<const float4*>(g_h + (size_t)row * D_HID + c4);

    // fused sum + sumsq reduction: warp shuffle, one smem round, one barrier
    float s  = v.x + v.y + v.z + v.w;
    float q2 = v.x * v.x + v.y * v.y + v.z * v.z + v.w * v.w;
#pragma unroll
    for (int o = 16; o; o >>= 1) {
        s  += __shfl_xor_sync(0xffffffffu, s, o);
        q2 += __shfl_xor_sync(0xffffffffu, q2, o);
    }
    __shared__ float red_s[4], red_q[4];
    if ((t & 31) == 0) { red_s[t >> 5] = s; red_q[t >> 5] = q2; }
    __syncthreads();
    float tot = red_s[0] + red_s[1] + red_s[2] + red_s[3];
    float qt  = red_q[0] + red_q[1] + red_q[2] + red_q[3];

    const float mean = tot * (1.0f / (float)D_HID);
    const float var  = qt * (1.0f / (float)D_HID) - mean * mean;
    const float inv  = rsqrtf(var + 1e-5f);

    float4 g4 = *reinterpret_cast<const float4*>(gamma + c4);
    float4 b4 = *reinterpret_cast<const float4*>(beta  + c4);

    const float y0 = (v.x - mean) * inv * g4.x + b4.x;
    const float y1 = (v.y - mean) * inv * g4.y + b4.y;
    const float y2 = (v.z - mean) * inv * g4.z + b4.z;
    const float y3 = (v.w - mean) * inv * g4.w + b4.w;

    float bs0[6], bs1[6], bs2[6], bs3[6];
    kan_bases(y0, bs0);
    kan_bases(y1, bs1);
    kan_bases(y2, bs2);
    kan_bases(y3, bs3);

    __half* dstp = g_A2 + ((size_t)row * K2 + c4);
    uint2 r;
    r.x = pk2(silu_f(y0), silu_f(y1));
    r.y = pk2(silu_f(y2), silu_f(y3));
    *reinterpret_cast<uint2*>(dstp) = r;
#pragma unroll
    for (int j = 0; j < 6; ++j) {
        r.x = pk2(bs0[j], bs1[j]);
        r.y = pk2(bs2[j], bs3[j]);
        *reinterpret_cast<uint2*>(dstp + (uint32_t)(j + 1) * D_HID) = r;
    }
}

// ---------------------------------------------------------------------------
// HMMA GEMM (frozen R9 config — at the mma.sync instruction ceiling):
// Block 128x128x64, 512 threads (16 warps = 4M x 4N), warp tile 32x32.
// 32 warps/SM at 2 CTAs/SM. 3-stage cp.async ring. 144B smem rows.
// ---------------------------------------------------------------------------
#define BM 128
#define BN 128
#define BK 64
#define ROWB 144u
#define STG_B (uint32_t)((BM + BN) * ROWB)   // 36864 B
#define NSTG 3

template <int L>
__global__ __launch_bounds__(512, 2) void gemm_hmma(float* __restrict__ Cparam) {
    constexpr int KK = (L == 1) ? K1 : K2;
    constexpr int NV = (L == 1) ? D_HID : D_OUT;
    constexpr int KT = KK / BK;

    const __half* __restrict__ A  = (L == 1) ? g_A1 : g_A2;
    const __half* __restrict__ Bw = (L == 1) ? g_W1 : g_W2;
    float* __restrict__ C         = (L == 1) ? g_h  : Cparam;

    extern __shared__ __half smh[];
    const uint32_t sbase = (uint32_t)__cvta_generic_to_shared(smh);

    const int tid  = threadIdx.x;
    const int warp = tid >> 5;
    const int lane = tid & 31;
    const int wm = (warp & 3) * 32;
    const int wn = (warp >> 2) * 32;
    const int mb = blockIdx.y;
    const int nb = blockIdx.x;

    const __half* Abase = A  + (size_t)(mb * BM) * KK;
    const __half* Bbase = Bw + (size_t)(nb * BN) * KK;

    auto issue = [&](int kt) {
        const uint32_t sb = sbase + (uint32_t)(kt % NSTG) * STG_B;
#pragma unroll
        for (int i = 0; i < 2; ++i) {
            const int idx = tid + i * 512;
            const int r = idx >> 3, c = idx & 7;
            const void* src = Abase + (size_t)r * KK + kt * BK + c * 8;
            const uint32_t dst = sb + (uint32_t)r * ROWB + (uint32_t)c * 16u;
            asm volatile("cp.async.cg.shared.global [%0], [%1], 16;"
                         :: "r"(dst), "l"(src));
        }
#pragma unroll
        for (int i = 0; i < 2; ++i) {
            const int idx = tid + i * 512;
            const int r = idx >> 3, c = idx & 7;
            const void* src = Bbase + (size_t)r * KK + kt * BK + c * 8;
            const uint32_t dst = sb + (uint32_t)BM * ROWB
                               + (uint32_t)r * ROWB + (uint32_t)c * 16u;
            asm volatile("cp.async.cg.shared.global [%0], [%1], 16;"
                         :: "r"(dst), "l"(src));
        }
        asm volatile("cp.async.commit_group;" ::: "memory");
    };

    float acc[2][4][4] = {};

    issue(0); issue(1);

    const int lrow = lane & 15;
    const int lcb  = (lane >> 4) * 8;

#pragma unroll 1
    for (int kt = 0; kt < KT; ++kt) {
        if (kt + 1 < KT) asm volatile("cp.async.wait_group 1;" ::: "memory");
        else             asm volatile("cp.async.wait_group 0;" ::: "memory");
        __syncthreads();
        if (kt + 2 < KT) issue(kt + 2);

        const uint32_t sb = sbase + (uint32_t)(kt % NSTG) * STG_B;
#pragma unroll
        for (int ks = 0; ks < 4; ++ks) {
            uint32_t a[2][4];
            uint32_t bq[2][4];
#pragma unroll
            for (int mt = 0; mt < 2; ++mt) {
                const uint32_t addr = sb + (uint32_t)(wm + mt * 16 + lrow) * ROWB
                                    + (uint32_t)(ks * 16 + lcb) * 2u;
                asm volatile("ldmatrix.sync.aligned.m8n8.x4.shared.b16 {%0,%1,%2,%3}, [%4];"
                             : "=r"(a[mt][0]), "=r"(a[mt][1]), "=r"(a[mt][2]), "=r"(a[mt][3])
                             : "r"(addr));
            }
#pragma unroll
            for (int np = 0; np < 2; ++np) {
                const uint32_t addr = sb + (uint32_t)BM * ROWB
                                    + (uint32_t)(wn + np * 16 + lrow) * ROWB
                                    + (uint32_t)(ks * 16 + lcb) * 2u;
                asm volatile("ldmatrix.sync.aligned.m8n8.x4.shared.b16 {%0,%1,%2,%3}, [%4];"
                             : "=r"(bq[np][0]), "=r"(bq[np][1]), "=r"(bq[np][2]), "=r"(bq[np][3])
                             : "r"(addr));
            }
#pragma unroll
            for (int mt = 0; mt < 2; ++mt) {
#pragma unroll
                for (int nt = 0; nt < 4; ++nt) {
                    const int np = nt >> 1, pp = nt & 1;
                    asm volatile(
                        "mma.sync.aligned.m16n8k16.row.col.f32.f16.f16.f32 "
                        "{%0,%1,%2,%3}, {%4,%5,%6,%7}, {%8,%9}, {%0,%1,%2,%3};"
                        : "+f"(acc[mt][nt][0]), "+f"(acc[mt][nt][1]),
                          "+f"(acc[mt][nt][2]), "+f"(acc[mt][nt][3])
                        : "r"(a[mt][0]), "r"(a[mt][1]), "r"(a[mt][2]), "r"(a[mt][3]),
                          "r"(bq[np][pp]), "r"(bq[np][pp + 2]));
                }
            }
        }
    }

    // ---- epilogue ----
    const int gr = lane >> 2;
    const int gc = (lane & 3) * 2;
#pragma unroll
    for (int mt = 0; mt < 2; ++mt) {
#pragma unroll
        for (int nt = 0; nt < 4; ++nt) {
            const int row = mb * BM + wm + mt * 16 + gr;
            const int col = nb * BN + wn + nt * 8 + gc;
            float* cp = C + (size_t)row * NV;
            if (NV % BN == 0) {
                cp[col]     = acc[mt][nt][0];
                cp[col + 1] = acc[mt][nt][1];
                cp += (size_t)8 * NV;
                cp[col]     = acc[mt][nt][2];
                cp[col + 1] = acc[mt][nt][3];
            } else {
                if (col < NV)     cp[col]     = acc[mt][nt][0];
                if (col + 1 < NV) cp[col + 1] = acc[mt][nt][1];
                cp += (size_t)8 * NV;
                if (col < NV)     cp[col]     = acc[mt][nt][2];
                if (col + 1 < NV) cp[col + 1] = acc[mt][nt][3];
            }
        }
    }
}

// ---------------------------------------------------------------------------
// Launch
// ---------------------------------------------------------------------------
#define GEMM_SMEM (NSTG * (int)STG_B)   // 110592 B

extern "C" void kernel_launch(void* const* d_in, const int* in_sizes, int n_in,
                              void* d_out, int out_size) {
    (void)in_sizes; (void)n_in; (void)out_size;
    const float* x   = (const float*)d_in[0];
    const float* bw1 = (const float*)d_in[1];
    const float* sw1 = (const float*)d_in[2];
    const float* sc1 = (const float*)d_in[3];
    const float* ga  = (const float*)d_in[4];
    const float* be  = (const float*)d_in[5];
    const float* bw2 = (const float*)d_in[6];
    const float* sw2 = (const float*)d_in[7];
    const float* sc2 = (const float*)d_in[8];
    float* out = (float*)d_out;

    cudaFuncSetAttribute(gemm_hmma<1>,
                         cudaFuncAttributeMaxDynamicSharedMemorySize, GEMM_SMEM);
    cudaFuncSetAttribute(gemm_hmma<2>,
                         cudaFuncAttributeMaxDynamicSharedMemorySize, GEMM_SMEM);

    // One merged prep launch: expand1 + fusew1 + fusew2
    prep_kernel<<<PREP_BLOCKS, 256>>>(x, bw1, sw1, sc1, bw2, sw2, sc2);

    // GEMM1: 512 CTAs (4 x 128)
    gemm_hmma<1><<<dim3(4, 128), 512, GEMM_SMEM>>>(nullptr);

    ln_expand2_kernel<<<B_SZ, 128>>>(ga, be);

    // GEMM2: 256 CTAs (2 x 128)
    gemm_hmma<2><<<dim3(2, 128), 512, GEMM_SMEM>>>(out);
}

// round 17
// speedup vs baseline: 1.4457x; 1.0002x over previous
#include <cuda_runtime.h>
#include <cuda_fp16.h>
#include <stdint.h>
#include <math.h>

// ---------------------------------------------------------------------------
// Problem dims
// ---------------------------------------------------------------------------
#define B_SZ   16384
#define D_IN   1280
#define D_HID  512
#define D_OUT  229
#define K1     (7 * D_IN)    // 8960
#define K2     (7 * D_HID)   // 3584
#define N2PAD  256

// ---------------------------------------------------------------------------
// Scratch
// ---------------------------------------------------------------------------
static __device__ __half g_A1[(size_t)B_SZ * K1];
static __device__ __half g_W1[(size_t)D_HID * K1];
static __device__ float  g_h [(size_t)B_SZ * D_HID];
static __device__ __half g_A2[(size_t)B_SZ * K2];
static __device__ __half g_W2[(size_t)N2PAD * K2];

// ---------------------------------------------------------------------------
// Closed-form uniform cubic B-spline bases — static indexing (spill-free, R9)
// ---------------------------------------------------------------------------
__device__ __forceinline__ void kan_bases(float x, float bs[6]) {
    const float s  = (x + 3.0f) * 1.5f;
    const float cf = floorf(s);
    const int   c  = (int)cf;
    const float u  = s - cf;
    const float u2 = u * u;
    const float u3 = u2 * u;
    const float om = 1.0f - u;
    const float seg0 = om * om * om * (1.0f / 6.0f);
    const float seg1 = (3.0f * u3 - 6.0f * u2 + 4.0f) * (1.0f / 6.0f);
    const float seg2 = (-3.0f * u3 + 3.0f * u2 + 3.0f * u + 1.0f) * (1.0f / 6.0f);
    const float seg3 = u3 * (1.0f / 6.0f);
#pragma unroll
    for (int j = 0; j < 6; ++j) {
        float v = 0.0f;
        v = (c == j    ) ? seg3 : v;
        v = (c == j + 1) ? seg2 : v;
        v = (c == j + 2) ? seg1 : v;
        v = (c == j + 3) ? seg0 : v;
        bs[j] = v;
    }
}

// silu via MUFU exp + fast divide (error ~1-2 ulp, far below the f16
// quantization applied immediately after)
__device__ __forceinline__ float silu_f(float v) {
    return __fdividef(v, 1.0f + __expf(-v));
}

__device__ __forceinline__ uint32_t pk2(float a, float b) {
    __half2 h = __floats2half2_rn(a, b);
    return *reinterpret_cast<uint32_t*>(&h);
}

// ---------------------------------------------------------------------------
// Merged prep kernel (R15 champion): expand1 (4 features/thread, uint2 stores)
// + fusew1 + fusew2.
// ---------------------------------------------------------------------------
#define E1_BLOCKS (B_SZ * (D_IN / 4) / 256)      // 20480
#define F1_BLOCKS (D_HID * D_IN / 256)            // 2560
#define F2_BLOCKS (N2PAD * D_HID / 256)           // 512
#define PREP_BLOCKS (E1_BLOCKS + F1_BLOCKS + F2_BLOCKS)

__global__ __launch_bounds__(256) void prep_kernel(
    const float* __restrict__ x,
    const float* __restrict__ bw1, const float* __restrict__ sw1,
    const float* __restrict__ sc1,
    const float* __restrict__ bw2, const float* __restrict__ sw2,
    const float* __restrict__ sc2)
{
    const int blk = blockIdx.x;
    if (blk < E1_BLOCKS) {
        uint32_t idx = (uint32_t)blk * 256u + threadIdx.x;   // over B_SZ * 320
        uint32_t b  = idx / (D_IN / 4);
        uint32_t i4 = (idx - b * (D_IN / 4)) * 4u;
        float4 v = *reinterpret_cast<const float4*>(x + (size_t)b * D_IN + i4);
        float bs0[6], bs1[6], bs2[6], bs3[6];
        kan_bases(v.x, bs0);
        kan_bases(v.y, bs1);
        kan_bases(v.z, bs2);
        kan_bases(v.w, bs3);
        __half* dstp = g_A1 + ((size_t)b * K1 + i4);
        uint2 r;
        r.x = pk2(silu_f(v.x), silu_f(v.y));
        r.y = pk2(silu_f(v.z), silu_f(v.w));
        *reinterpret_cast<uint2*>(dstp) = r;
#pragma unroll
        for (int j = 0; j < 6; ++j) {
            r.x = pk2(bs0[j], bs1[j]);
            r.y = pk2(bs2[j], bs3[j]);
            *reinterpret_cast<uint2*>(dstp + (uint32_t)(j + 1) * D_IN) = r;
        }
    } else if (blk < E1_BLOCKS + F1_BLOCKS) {
        uint32_t idx = (uint32_t)(blk - E1_BLOCKS) * 256u + threadIdx.x;
        uint32_t o = idx / D_IN;
        uint32_t i = idx - o * D_IN;
        uint32_t base = o * (uint32_t)K1 + i;
        g_W1[base] = __float2half(bw1[idx]);
        float s = sc1[idx];
#pragma unroll
        for (int j = 0; j < 6; ++j)
            g_W1[base + (uint32_t)(j + 1) * D_IN] =
                __float2half(sw1[(size_t)idx * 6 + j] * s);
    } else {
        uint32_t idx = (uint32_t)(blk - E1_BLOCKS - F1_BLOCKS) * 256u + threadIdx.x;
        uint32_t o = idx / D_HID;
        uint32_t c = idx - o * D_HID;
        uint32_t base = o * (uint32_t)K2 + c;
        if (o < D_OUT) {
            uint32_t widx = o * (uint32_t)D_HID + c;
            g_W2[base] = __float2half(bw2[widx]);
            float s = sc2[widx];
#pragma unroll
            for (int j = 0; j < 6; ++j)
                g_W2[base + (uint32_t)(j + 1) * D_HID] =
                    __float2half(sw2[(size_t)widx * 6 + j] * s);
        } else {
            g_W2[base] = __float2half(0.0f);
#pragma unroll
            for (int j = 0; j < 6; ++j)
                g_W2[base + (uint32_t)(j + 1) * D_HID] = __float2half(0.0f);
        }
    }
}

// ---------------------------------------------------------------------------
// LayerNorm + expansion: TWO rows per 128-thread block (thread t holds 4 cols
// of row 2b and row 2b+1 -> MLP=2 on the g_h loads; both rows' reductions
// share ONE __syncthreads). uint2 stores, fused sum+sumsq shuffle reduction.
// ---------------------------------------------------------------------------
__global__ __launch_bounds__(128) void ln_expand2_kernel(
    const float* __restrict__ gamma, const float* __restrict__ beta)
{
    const int row0 = blockIdx.x * 2;
    const int t    = threadIdx.x;
    const int c4   = t * 4;

    const float* h0 = g_h + (size_t)row0 * D_HID + c4;
    float4 va = *reinterpret_cast<const float4*>(h0);
    float4 vb = *reinterpret_cast<const float4*>(h0 + D_HID);

    float sa  = va.x + va.y + va.z + va.w;
    float qa  = va.x * va.x + va.y * va.y + va.z * va.z + va.w * va.w;
    float sb  = vb.x + vb.y + vb.z + vb.w;
    float qb  = vb.x * vb.x + vb.y * vb.y + vb.z * vb.z + vb.w * vb.w;
#pragma unroll
    for (int o = 16; o; o >>= 1) {
        sa += __shfl_xor_sync(0xffffffffu, sa, o);
        qa += __shfl_xor_sync(0xffffffffu, qa, o);
        sb += __shfl_xor_sync(0xffffffffu, sb, o);
        qb += __shfl_xor_sync(0xffffffffu, qb, o);
    }
    __shared__ float red[4][4];   // [quantity][warp]
    if ((t & 31) == 0) {
        const int w = t >> 5;
        red[0][w] = sa; red[1][w] = qa; red[2][w] = sb; red[3][w] = qb;
    }
    __syncthreads();
    const float tot_a = red[0][0] + red[0][1] + red[0][2] + red[0][3];
    const float qt_a  = red[1][0] + red[1][1] + red[1][2] + red[1][3];
    const float tot_b = red[2][0] + red[2][1] + red[2][2] + red[2][3];
    const float qt_b  = red[3][0] + red[3][1] + red[3][2] + red[3][3];

    const float mean_a = tot_a * (1.0f / (float)D_HID);
    const float inv_a  = rsqrtf(qt_a * (1.0f / (float)D_HID) - mean_a * mean_a + 1e-5f);
    const float mean_b = tot_b * (1.0f / (float)D_HID);
    const float inv_b  = rsqrtf(qt_b * (1.0f / (float)D_HID) - mean_b * mean_b + 1e-5f);

    const float4 g4 = *reinterpret_cast<const float4*>(gamma + c4);
    const float4 b4 = *reinterpret_cast<const float4*>(beta  + c4);

#pragma unroll
    for (int rr = 0; rr < 2; ++rr) {
        const float4 v   = (rr == 0) ? va : vb;
        const float mean = (rr == 0) ? mean_a : mean_b;
        const float inv  = (rr == 0) ? inv_a  : inv_b;

        const float y0 = (v.x - mean) * inv * g4.x + b4.x;
        const float y1 = (v.y - mean) * inv * g4.y + b4.y;
        const float y2 = (v.z - mean) * inv * g4.z + b4.z;
        const float y3 = (v.w - mean) * inv * g4.w + b4.w;

        float bs0[6], bs1[6], bs2[6], bs3[6];
        kan_bases(y0, bs0);
        kan_bases(y1, bs1);
        kan_bases(y2, bs2);
        kan_bases(y3, bs3);

        __half* dstp = g_A2 + ((size_t)(row0 + rr) * K2 + c4);
        uint2 r;
        r.x = pk2(silu_f(y0), silu_f(y1));
        r.y = pk2(silu_f(y2), silu_f(y3));
        *reinterpret_cast<uint2*>(dstp) = r;
#pragma unroll
        for (int j = 0; j < 6; ++j) {
            r.x = pk2(bs0[j], bs1[j]);
            r.y = pk2(bs2[j], bs3[j]);
            *reinterpret_cast<uint2*>(dstp + (uint32_t)(j + 1) * D_HID) = r;
        }
    }
}

// ---------------------------------------------------------------------------
// HMMA GEMM (frozen R9 config — at the mma.sync instruction ceiling):
// Block 128x128x64, 512 threads (16 warps = 4M x 4N), warp tile 32x32.
// 32 warps/SM at 2 CTAs/SM. 3-stage cp.async ring. 144B smem rows.
// ---------------------------------------------------------------------------
#define BM 128
#define BN 128
#define BK 64
#define ROWB 144u
#define STG_B (uint32_t)((BM + BN) * ROWB)   // 36864 B
#define NSTG 3

template <int L>
__global__ __launch_bounds__(512, 2) void gemm_hmma(float* __restrict__ Cparam) {
    constexpr int KK = (L == 1) ? K1 : K2;
    constexpr int NV = (L == 1) ? D_HID : D_OUT;
    constexpr int KT = KK / BK;

    const __half* __restrict__ A  = (L == 1) ? g_A1 : g_A2;
    const __half* __restrict__ Bw = (L == 1) ? g_W1 : g_W2;
    float* __restrict__ C         = (L == 1) ? g_h  : Cparam;

    extern __shared__ __half smh[];
    const uint32_t sbase = (uint32_t)__cvta_generic_to_shared(smh);

    const int tid  = threadIdx.x;
    const int warp = tid >> 5;
    const int lane = tid & 31;
    const int wm = (warp & 3) * 32;
    const int wn = (warp >> 2) * 32;
    const int mb = blockIdx.y;
    const int nb = blockIdx.x;

    const __half* Abase = A  + (size_t)(mb * BM) * KK;
    const __half* Bbase = Bw + (size_t)(nb * BN) * KK;

    auto issue = [&](int kt) {
        const uint32_t sb = sbase + (uint32_t)(kt % NSTG) * STG_B;
#pragma unroll
        for (int i = 0; i < 2; ++i) {
            const int idx = tid + i * 512;
            const int r = idx >> 3, c = idx & 7;
            const void* src = Abase + (size_t)r * KK + kt * BK + c * 8;
            const uint32_t dst = sb + (uint32_t)r * ROWB + (uint32_t)c * 16u;
            asm volatile("cp.async.cg.shared.global [%0], [%1], 16;"
                         :: "r"(dst), "l"(src));
        }
#pragma unroll
        for (int i = 0; i < 2; ++i) {
            const int idx = tid + i * 512;
            const int r = idx >> 3, c = idx & 7;
            const void* src = Bbase + (size_t)r * KK + kt * BK + c * 8;
            const uint32_t dst = sb + (uint32_t)BM * ROWB
                               + (uint32_t)r * ROWB + (uint32_t)c * 16u;
            asm volatile("cp.async.cg.shared.global [%0], [%1], 16;"
                         :: "r"(dst), "l"(src));
        }
        asm volatile("cp.async.commit_group;" ::: "memory");
    };

    float acc[2][4][4] = {};

    issue(0); issue(1);

    const int lrow = lane & 15;
    const int lcb  = (lane >> 4) * 8;

#pragma unroll 1
    for (int kt = 0; kt < KT; ++kt) {
        if (kt + 1 < KT) asm volatile("cp.async.wait_group 1;" ::: "memory");
        else             asm volatile("cp.async.wait_group 0;" ::: "memory");
        __syncthreads();
        if (kt + 2 < KT) issue(kt + 2);

        const uint32_t sb = sbase + (uint32_t)(kt % NSTG) * STG_B;
#pragma unroll
        for (int ks = 0; ks < 4; ++ks) {
            uint32_t a[2][4];
            uint32_t bq[2][4];
#pragma unroll
            for (int mt = 0; mt < 2; ++mt) {
                const uint32_t addr = sb + (uint32_t)(wm + mt * 16 + lrow) * ROWB
                                    + (uint32_t)(ks * 16 + lcb) * 2u;
                asm volatile("ldmatrix.sync.aligned.m8n8.x4.shared.b16 {%0,%1,%2,%3}, [%4];"
                             : "=r"(a[mt][0]), "=r"(a[mt][1]), "=r"(a[mt][2]), "=r"(a[mt][3])
                             : "r"(addr));
            }
#pragma unroll
            for (int np = 0; np < 2; ++np) {
                const uint32_t addr = sb + (uint32_t)BM * ROWB
                                    + (uint32_t)(wn + np * 16 + lrow) * ROWB
                                    + (uint32_t)(ks * 16 + lcb) * 2u;
                asm volatile("ldmatrix.sync.aligned.m8n8.x4.shared.b16 {%0,%1,%2,%3}, [%4];"
                             : "=r"(bq[np][0]), "=r"(bq[np][1]), "=r"(bq[np][2]), "=r"(bq[np][3])
                             : "r"(addr));
            }
#pragma unroll
            for (int mt = 0; mt < 2; ++mt) {
#pragma unroll
                for (int nt = 0; nt < 4; ++nt) {
                    const int np = nt >> 1, pp = nt & 1;
                    asm volatile(
                        "mma.sync.aligned.m16n8k16.row.col.f32.f16.f16.f32 "
                        "{%0,%1,%2,%3}, {%4,%5,%6,%7}, {%8,%9}, {%0,%1,%2,%3};"
                        : "+f"(acc[mt][nt][0]), "+f"(acc[mt][nt][1]),
                          "+f"(acc[mt][nt][2]), "+f"(acc[mt][nt][3])
                        : "r"(a[mt][0]), "r"(a[mt][1]), "r"(a[mt][2]), "r"(a[mt][3]),
                          "r"(bq[np][pp]), "r"(bq[np][pp + 2]));
                }
            }
        }
    }

    // ---- epilogue ----
    const int gr = lane >> 2;
    const int gc = (lane & 3) * 2;
#pragma unroll
    for (int mt = 0; mt < 2; ++mt) {
#pragma unroll
        for (int nt = 0; nt < 4; ++nt) {
            const int row = mb * BM + wm + mt * 16 + gr;
            const int col = nb * BN + wn + nt * 8 + gc;
            float* cp = C + (size_t)row * NV;
            if (NV % BN == 0) {
                cp[col]     = acc[mt][nt][0];
                cp[col + 1] = acc[mt][nt][1];
                cp += (size_t)8 * NV;
                cp[col]     = acc[mt][nt][2];
                cp[col + 1] = acc[mt][nt][3];
            } else {
                if (col < NV)     cp[col]     = acc[mt][nt][0];
                if (col + 1 < NV) cp[col + 1] = acc[mt][nt][1];
                cp += (size_t)8 * NV;
                if (col < NV)     cp[col]     = acc[mt][nt][2];
                if (col + 1 < NV) cp[col + 1] = acc[mt][nt][3];
            }
        }
    }
}

// ---------------------------------------------------------------------------
// Launch
// ---------------------------------------------------------------------------
#define GEMM_SMEM (NSTG * (int)STG_B)   // 110592 B

extern "C" void kernel_launch(void* const* d_in, const int* in_sizes, int n_in,
                              void* d_out, int out_size) {
    (void)in_sizes; (void)n_in; (void)out_size;
    const float* x   = (const float*)d_in[0];
    const float* bw1 = (const float*)d_in[1];
    const float* sw1 = (const float*)d_in[2];
    const float* sc1 = (const float*)d_in[3];
    const float* ga  = (const float*)d_in[4];
    const float* be  = (const float*)d_in[5];
    const float* bw2 = (const float*)d_in[6];
    const float* sw2 = (const float*)d_in[7];
    const float* sc2 = (const float*)d_in[8];
    float* out = (float*)d_out;

    cudaFuncSetAttribute(gemm_hmma<1>,
                         cudaFuncAttributeMaxDynamicSharedMemorySize, GEMM_SMEM);
    cudaFuncSetAttribute(gemm_hmma<2>,
                         cudaFuncAttributeMaxDynamicSharedMemorySize, GEMM_SMEM);

    // One merged prep launch: expand1 + fusew1 + fusew2
    prep_kernel<<<PREP_BLOCKS, 256>>>(x, bw1, sw1, sc1, bw2, sw2, sc2);

    // GEMM1: 512 CTAs (4 x 128)
    gemm_hmma<1><<<dim3(4, 128), 512, GEMM_SMEM>>>(nullptr);

    ln_expand2_kernel<<<B_SZ / 2, 128>>>(ga, be);

    // GEMM2: 256 CTAs (2 x 128)
    gemm_hmma<2><<<dim3(2, 128), 512, GEMM_SMEM>>>(out);
}